// round 12
// baseline (speedup 1.0000x reference)
#include <cuda_runtime.h>
#include <cuda_bf16.h>
#include <cuda_fp16.h>
#include <math.h>
#include <stdint.h>

#define L 4096
#define DM 1024
#define DIN 2048
#define NH 32
#define HD 64
#define NST 128
#define CONVD 2560
#define DPROJ 4672
#define CHK 128
#define NC 32
#define EPSV 1e-5f

// ---------------- scratch (static device globals; no allocation) ----------------
__device__ float g_zx[(size_t)L * DPROJ];
__device__ float g_xc[(size_t)L * CONVD];
__device__ float g_dt2[2 * L * NH];
__device__ float g_Bm[(size_t)2 * L * NST];
__device__ float g_Cm[(size_t)2 * L * NST];
__device__ float g_Acs[2 * NC * NH * CHK];
__device__ float g_G[(size_t)2 * NC * CHK * CHK];
__device__ float g_Yd[(size_t)2 * L * DIN];
__device__ float g_states[(size_t)2 * NC * NH * HD * NST];
__device__ float g_fd[L * NH];

__device__ __align__(16) __half g_uh[(size_t)L * DM];
__device__ __align__(16) __half g_ul[(size_t)L * DM];
__device__ __align__(16) __half g_wi[(size_t)DPROJ * DM];
__device__ __align__(16) __half g_ynh[(size_t)L * DIN];
__device__ __align__(16) __half g_ynl[(size_t)L * DIN];
__device__ __align__(16) __half g_wo[(size_t)DM * DIN];

__device__ __forceinline__ float sigmoidf_(float x) { return 1.f / (1.f + __expf(-x)); }

__device__ __forceinline__ uint32_t smem_u32(const void* p) {
    uint32_t a;
    asm("{ .reg .u64 tmp; cvta.to.shared.u64 tmp, %1; cvt.u32.u64 %0, tmp; }" : "=r"(a) : "l"(p));
    return a;
}
__device__ __forceinline__ void cp_async16(uint32_t dst, const void* src, int srcsize) {
    asm volatile("cp.async.cg.shared.global [%0], [%1], 16, %2;"
                 :: "r"(dst), "l"(src), "r"(srcsize));
}
#define CP_COMMIT() asm volatile("cp.async.commit_group;" ::: "memory")
#define CP_WAIT1()  asm volatile("cp.async.wait_group 1;"  ::: "memory")
#define CP_WAIT0()  asm volatile("cp.async.wait_group 0;"  ::: "memory")

__device__ __forceinline__ void ldsm4(uint32_t* r, uint32_t addr) {
    asm volatile("ldmatrix.sync.aligned.m8n8.x4.shared.b16 {%0,%1,%2,%3}, [%4];"
                 : "=r"(r[0]), "=r"(r[1]), "=r"(r[2]), "=r"(r[3]) : "r"(addr));
}
__device__ __forceinline__ void mma16816h(float* c, const uint32_t* a, uint32_t b0, uint32_t b1) {
    asm volatile("mma.sync.aligned.m16n8k16.row.col.f32.f16.f16.f32 "
                 "{%0,%1,%2,%3}, {%4,%5,%6,%7}, {%8,%9}, {%0,%1,%2,%3};"
                 : "+f"(c[0]), "+f"(c[1]), "+f"(c[2]), "+f"(c[3])
                 : "r"(a[0]), "r"(a[1]), "r"(a[2]), "r"(a[3]), "r"(b0), "r"(b1));
}
__device__ __forceinline__ void split_hilo_h(float v, __half& h, __half& l) {
    h = __float2half(v);
    l = __float2half(v - __half2float(h));
}

// ---------------- fp32 -> fp16 hi/lo split ----------------
__global__ void cvt_hilo_kernel(const float* __restrict__ x,
                                __half* __restrict__ hi,
                                __half* __restrict__ lo, size_t n) {
    size_t i = (size_t)blockIdx.x * blockDim.x + threadIdx.x;
    if (i >= n) return;
    __half h, lv;
    split_hilo_h(x[i], h, lv);
    hi[i] = h; lo[i] = lv;
}
__global__ void cvt_h_kernel(const float* __restrict__ x, __half* __restrict__ o, size_t n) {
    size_t i = (size_t)blockIdx.x * blockDim.x + threadIdx.x;
    if (i >= n) return;
    o[i] = __float2half(x[i]);
}

// ===== mma.sync fp16 2-term GEMM, 2-stage cp.async pipeline (proven) =====
#define KC 32
#define APAD 40

__global__ __launch_bounds__(256, 2) void gemm_2t(
    const __half* __restrict__ Ah, const __half* __restrict__ Al,
    const __half* __restrict__ Bw,
    float* __restrict__ Cc, int Ntot, int Ktot) {
    extern __shared__ __align__(16) __half sm[];
    const int tid = threadIdx.x;
    const int bRow = blockIdx.y * 128, bCol = blockIdx.x * 128;
    const int wid = tid >> 5, lane = tid & 31;
    const int wm = (wid >> 2) * 64, wn = (wid & 3) * 32;

    __half* sp[2][3];
#pragma unroll
    for (int s = 0; s < 2; s++)
#pragma unroll
        for (int o = 0; o < 3; o++) sp[s][o] = sm + ((s * 3 + o) * 128 * APAD);

    float acc[4][4][4];
#pragma unroll
    for (int i = 0; i < 4; i++)
#pragma unroll
        for (int j = 0; j < 4; j++)
#pragma unroll
            for (int q = 0; q < 4; q++) acc[i][j][q] = 0.f;

    const int nst = Ktot / KC;

    auto issue = [&](int s, int c) {
        int kt = c * KC;
#pragma unroll
        for (int i = 0; i < 2; i++) {
            int u = tid + i * 256;
            int r = u >> 2, kc = (u & 3) * 8;
            size_t ga = (size_t)(bRow + r) * Ktot + kt + kc;
            cp_async16(smem_u32(sp[s][0] + r * APAD + kc), Ah + ga, 16);
            cp_async16(smem_u32(sp[s][1] + r * APAD + kc), Al + ga, 16);
            int ok = (bCol + r) < Ntot ? 16 : 0;
            size_t gb = ok ? ((size_t)(bCol + r) * Ktot + kt + kc) : 0;
            cp_async16(smem_u32(sp[s][2] + r * APAD + kc), Bw + gb, ok);
        }
    };

    issue(0, 0);
    CP_COMMIT();

    const int ar = lane & 15, ac = (lane >> 4) * 8;
    for (int c = 0; c < nst; c++) {
        if (c + 1 < nst) { issue((c + 1) & 1, c + 1); CP_COMMIT(); CP_WAIT1(); }
        else CP_WAIT0();
        __syncthreads();
        const __half* sa_h = sp[c & 1][0];
        const __half* sa_l = sp[c & 1][1];
        const __half* sb   = sp[c & 1][2];
#pragma unroll
        for (int kk = 0; kk < 2; kk++) {
            int k0 = kk * 16;
            uint32_t bf[2][4];
#pragma unroll
            for (int bt = 0; bt < 2; bt++)
                ldsm4(bf[bt], smem_u32(sb + (wn + bt * 16 + ar) * APAD + k0 + ac));
#pragma unroll
            for (int mt = 0; mt < 4; mt++) {
                uint32_t afh[4], afl[4];
                ldsm4(afh, smem_u32(sa_h + (wm + mt * 16 + ar) * APAD + k0 + ac));
                ldsm4(afl, smem_u32(sa_l + (wm + mt * 16 + ar) * APAD + k0 + ac));
#pragma unroll
                for (int nt = 0; nt < 4; nt++) {
                    int bt = nt >> 1, sel = nt & 1;
                    mma16816h(acc[mt][nt], afh, bf[bt][sel], bf[bt][sel + 2]);
                }
#pragma unroll
                for (int nt = 0; nt < 4; nt++) {
                    int bt = nt >> 1, sel = nt & 1;
                    mma16816h(acc[mt][nt], afl, bf[bt][sel], bf[bt][sel + 2]);
                }
            }
        }
        __syncthreads();
    }

    const int g = lane >> 2, t4 = lane & 3;
#pragma unroll
    for (int mt = 0; mt < 4; mt++) {
#pragma unroll
        for (int nt = 0; nt < 4; nt++) {
            int row = bRow + wm + mt * 16 + g;
            int col = bCol + wn + nt * 8 + t4 * 2;
            if (col < Ntot) {
                float* p0 = Cc + (size_t)row * Ntot + col;
                p0[0] = acc[mt][nt][0];
                p0[1] = acc[mt][nt][1];
                float* p1 = p0 + (size_t)8 * Ntot;
                p1[0] = acc[mt][nt][2];
                p1[1] = acc[mt][nt][3];
            }
        }
    }
}

// ---------------- 64x64-tile batched NT SGEMM for G = C B^T ----------------
__global__ __launch_bounds__(256) void sgemm64_nt(const float* __restrict__ A,
                                                  const float* __restrict__ B,
                                                  float* __restrict__ C) {
    A += (size_t)blockIdx.z * CHK * NST;
    B += (size_t)blockIdx.z * CHK * NST;
    C += (size_t)blockIdx.z * CHK * CHK;
    __shared__ float As[16][68];
    __shared__ float Bs[16][68];
    int tid = threadIdx.x;
    int bRow = blockIdx.y * 64, bCol = blockIdx.x * 64;
    int tx = tid & 15, ty = tid >> 4;
    float acc[4][4] = {};
    int lr = tid >> 2, lk = (tid & 3) * 4;
    for (int kt = 0; kt < NST; kt += 16) {
        {
            float4 v = *(const float4*)(A + (size_t)(bRow + lr) * NST + kt + lk);
            As[lk][lr] = v.x; As[lk + 1][lr] = v.y; As[lk + 2][lr] = v.z; As[lk + 3][lr] = v.w;
            float4 w = *(const float4*)(B + (size_t)(bCol + lr) * NST + kt + lk);
            Bs[lk][lr] = w.x; Bs[lk + 1][lr] = w.y; Bs[lk + 2][lr] = w.z; Bs[lk + 3][lr] = w.w;
        }
        __syncthreads();
#pragma unroll
        for (int k = 0; k < 16; k++) {
            float4 ra = *(const float4*)&As[k][ty * 4];
            float4 rb = *(const float4*)&Bs[k][tx * 4];
            float a0 = ra.x, a1 = ra.y, a2 = ra.z, a3 = ra.w;
            acc[0][0] += a0 * rb.x; acc[0][1] += a0 * rb.y; acc[0][2] += a0 * rb.z; acc[0][3] += a0 * rb.w;
            acc[1][0] += a1 * rb.x; acc[1][1] += a1 * rb.y; acc[1][2] += a1 * rb.z; acc[1][3] += a1 * rb.w;
            acc[2][0] += a2 * rb.x; acc[2][1] += a2 * rb.y; acc[2][2] += a2 * rb.z; acc[2][3] += a2 * rb.w;
            acc[3][0] += a3 * rb.x; acc[3][1] += a3 * rb.y; acc[3][2] += a3 * rb.z; acc[3][3] += a3 * rb.w;
        }
        __syncthreads();
    }
#pragma unroll
    for (int i = 0; i < 4; i++) {
        float* p = C + (size_t)(bRow + ty * 4 + i) * CHK + bCol + tx * 4;
        p[0] = acc[i][0]; p[1] = acc[i][1]; p[2] = acc[i][2]; p[3] = acc[i][3];
    }
}

// ---------------- depthwise causal conv (k=4) + bias + silu ----------------
__global__ void conv_kernel(const float* __restrict__ cw, const float* __restrict__ cb) {
    size_t idx = (size_t)blockIdx.x * blockDim.x + threadIdx.x;
    if (idx >= (size_t)L * CONVD) return;
    int c = (int)(idx % CONVD);
    int t = (int)(idx / CONVD);
    float acc = cb[c];
#pragma unroll
    for (int k = 0; k < 4; k++) {
        int ts = t - 3 + k;
        if (ts >= 0) acc += cw[c * 4 + k] * g_zx[(size_t)ts * DPROJ + DIN + c];
    }
    g_xc[idx] = acc * sigmoidf_(acc);
}

// ---------------- dt (with direction flip) + softplus ----------------
__global__ void dt_kernel(const float* __restrict__ dt_bias) {
    int idx = blockIdx.x * blockDim.x + threadIdx.x;
    if (idx >= 2 * L * NH) return;
    int h = idx & 31;
    int t = (idx >> 5) & (L - 1);
    int dir = idx >> 17;
    int ts = dir ? (L - 1 - t) : t;
    float v = g_zx[(size_t)ts * DPROJ + DIN + CONVD + dir * NH + h] + dt_bias[h];
    g_dt2[idx] = (v > 20.f) ? v : log1pf(expf(v));
}

// ---------------- B/C split per direction (flip for dir1) ----------------
__global__ void prep_bc_kernel() {
    int idx = blockIdx.x * blockDim.x + threadIdx.x;
    if (idx >= 2 * L * NST) return;
    int n = idx & 127;
    int t = (idx >> 7) & (L - 1);
    int dir = idx >> 19;
    int ts = dir ? (L - 1 - t) : t;
    int off = dir ? 256 : 0;
    const float* p = g_xc + (size_t)ts * CONVD + DIN + off;
    g_Bm[idx] = p[n];
    g_Cm[idx] = p[NST + n];
}

// ---------------- per-chunk cumsum of A*dt ----------------
__global__ void acs_kernel(const float* __restrict__ A_log) {
    int c = blockIdx.x, dir = blockIdx.y, h = threadIdx.x;
    float Ah = -expf(A_log[h]);
    float cum = 0.f;
    float* out = g_Acs + (((dir * NC + c) * NH + h) << 7);
    const float* dtp = g_dt2 + ((size_t)(dir * L + c * CHK)) * NH + h;
    for (int l = 0; l < CHK; l++) {
        cum += Ah * dtp[l * NH];
        out[l] = cum;
    }
}

// ======== tensor-core SSD chunk kernels (fp16 mma; M single-fp16, X/S hi-lo split) ====
#define YD_ACS 0
#define YD_DT  512
#define YD_CV  1024
#define YD_R   1536
#define YD_M   5632
#define YD_XH  (YD_M + 128 * 136 * 2)    // 40448
#define YD_XL  (YD_XH + 64 * 136 * 2)    // 57856
#define YD_SMEM (YD_XL + 64 * 136 * 2)   // 75264

__global__ __launch_bounds__(256) void ydiag_states_tc() {
    extern __shared__ __align__(16) char smc[];
    float* sAcs = (float*)(smc + YD_ACS);
    float* sDt  = (float*)(smc + YD_DT);
    float* sCv  = (float*)(smc + YD_CV);
    float (*sR)[8] = (float(*)[8])(smc + YD_R);
    __half* sM  = (__half*)(smc + YD_M);
    __half* sXh = (__half*)(smc + YD_XH);
    __half* sXl = (__half*)(smc + YD_XL);

    const int b = blockIdx.x;
    const int h = b & 31, c = (b >> 5) & 31, dir = b >> 10;
    const int tid = threadIdx.x;
    const int wid = tid >> 5, lane = tid & 31;
    const int m0 = wid * 16;
    const int ar = lane & 15, ac = (lane >> 4) * 8;
    const int g = lane >> 2, t4 = lane & 3;

    if (tid < CHK) {
        sAcs[tid] = g_Acs[(b << 7) + tid];
        sDt[tid] = g_dt2[((size_t)(dir * L + c * CHK + tid)) * NH + h];
    }
    __syncthreads();
    if (tid < CHK) sCv[tid] = __expf(sAcs[tid | 15] - sAcs[tid]);
    {
        int i0 = tid * 4;
#pragma unroll
        for (int q = 0; q < 4; q++) {
            int idx = i0 + q;
            int l = idx >> 3, st = idx & 7;
            sR[l][st] = __expf(fminf(sAcs[l] - sAcs[st * 16 + 15], 85.f));
        }
    }
    __syncthreads();

    const float* Gp = g_G + ((size_t)(dir * NC + c) << 14);
    // build M (masked decay * G) as fp16, row-major [l][s]
    {
        const int l = tid >> 1;
        const int s0 = (tid & 1) * 64;
        const float* gp = Gp + (size_t)l * CHK + s0;
        __half* mrow = sM + l * 136;
#pragma unroll 4
        for (int j = 0; j < 16; j++) {
            int s = s0 + j * 4;
            float4 gv = *(const float4*)(gp + j * 4);
            float rr = sR[l][s >> 4];
            float v0 = (l >= s)     ? gv.x * rr * sCv[s]     : 0.f;
            float v1 = (l >= s + 1) ? gv.y * rr * sCv[s + 1] : 0.f;
            float v2 = (l >= s + 2) ? gv.z * rr * sCv[s + 2] : 0.f;
            float v3 = (l >= s + 3) ? gv.w * rr * sCv[s + 3] : 0.f;
            *(__half2*)(mrow + s)     = __floats2half2_rn(v0, v1);
            *(__half2*)(mrow + s + 2) = __floats2half2_rn(v2, v3);
        }
    }
    // build X = x*dt transposed [p][l] as hi/lo
    {
        const int l = tid >> 1;
        const int p0 = (tid & 1) * 32;
        float dtv = sDt[l];
        int tg = c * CHK + l;
        int ts = dir ? (L - 1 - tg) : tg;
        const float* xr = g_xc + (size_t)ts * CONVD + h * HD + p0;
#pragma unroll
        for (int j = 0; j < 8; j++) {
            float4 v = *(const float4*)(xr + j * 4);
            float xs[4] = {v.x * dtv, v.y * dtv, v.z * dtv, v.w * dtv};
#pragma unroll
            for (int i = 0; i < 4; i++) {
                int p = p0 + j * 4 + i;
                __half hv = __float2half(xs[i]);
                sXh[p * 136 + l] = hv;
                sXl[p * 136 + l] = __float2half(xs[i] - __half2float(hv));
            }
        }
    }
    __syncthreads();

    // matmul 1: Y[l][p] = M @ (Xh + Xl)
    {
        float acc[8][4] = {};
#pragma unroll
        for (int kk = 0; kk < 8; kk++) {
            int k0 = kk * 16;
            uint32_t af[4];
            ldsm4(af, smem_u32(sM + (m0 + ar) * 136 + k0 + ac));
            uint32_t bh[4][4], blo[4][4];
#pragma unroll
            for (int bt = 0; bt < 4; bt++) {
                ldsm4(bh[bt],  smem_u32(sXh + (bt * 16 + ar) * 136 + k0 + ac));
                ldsm4(blo[bt], smem_u32(sXl + (bt * 16 + ar) * 136 + k0 + ac));
            }
#pragma unroll
            for (int nt = 0; nt < 8; nt++) {
                int bt = nt >> 1, sel = nt & 1;
                mma16816h(acc[nt], af, bh[bt][sel], bh[bt][sel + 2]);
            }
#pragma unroll
            for (int nt = 0; nt < 8; nt++) {
                int bt = nt >> 1, sel = nt & 1;
                mma16816h(acc[nt], af, blo[bt][sel], blo[bt][sel + 2]);
            }
        }
        float* Yp = g_Yd + ((size_t)(dir * L + c * CHK)) * DIN + h * HD;
#pragma unroll
        for (int nt = 0; nt < 8; nt++) {
            int p = nt * 8 + t4 * 2;
            int l = m0 + g;
            Yp[(size_t)l * DIN + p]           = acc[nt][0];
            Yp[(size_t)l * DIN + p + 1]       = acc[nt][1];
            Yp[(size_t)(l + 8) * DIN + p]     = acc[nt][2];
            Yp[(size_t)(l + 8) * DIN + p + 1] = acc[nt][3];
        }
    }
    __syncthreads();

    // rebuild sM with Bdec^T [n][l]
    {
        const int l = tid >> 1;
        const int n0 = (tid & 1) * 64;
        float dec = __expf(sAcs[127] - sAcs[l]);
        const float* Bp = g_Bm + ((size_t)(dir * L + c * CHK) + l) * NST + n0;
#pragma unroll
        for (int j = 0; j < 16; j++) {
            float4 v = *(const float4*)(Bp + j * 4);
            int n = n0 + j * 4;
            sM[(n)     * 136 + l] = __float2half(v.x * dec);
            sM[(n + 1) * 136 + l] = __float2half(v.y * dec);
            sM[(n + 2) * 136 + l] = __float2half(v.z * dec);
            sM[(n + 3) * 136 + l] = __float2half(v.w * dec);
        }
    }
    __syncthreads();

    // matmul 2: states[n][p] = Bdec^T @ (Xh + Xl), stored as [p][n]
    {
        float acc[8][4] = {};
#pragma unroll
        for (int kk = 0; kk < 8; kk++) {
            int k0 = kk * 16;
            uint32_t af[4];
            ldsm4(af, smem_u32(sM + (m0 + ar) * 136 + k0 + ac));
            uint32_t bh[4][4], blo[4][4];
#pragma unroll
            for (int bt = 0; bt < 4; bt++) {
                ldsm4(bh[bt],  smem_u32(sXh + (bt * 16 + ar) * 136 + k0 + ac));
                ldsm4(blo[bt], smem_u32(sXl + (bt * 16 + ar) * 136 + k0 + ac));
            }
#pragma unroll
            for (int nt = 0; nt < 8; nt++) {
                int bt = nt >> 1, sel = nt & 1;
                mma16816h(acc[nt], af, bh[bt][sel], bh[bt][sel + 2]);
            }
#pragma unroll
            for (int nt = 0; nt < 8; nt++) {
                int bt = nt >> 1, sel = nt & 1;
                mma16816h(acc[nt], af, blo[bt][sel], blo[bt][sel + 2]);
            }
        }
        float* Sp = g_states + ((size_t)b << 13);
#pragma unroll
        for (int nt = 0; nt < 8; nt++) {
            int p = nt * 8 + t4 * 2;
            int n = m0 + g;
            Sp[(size_t)p * NST + n]           = acc[nt][0];
            Sp[(size_t)(p + 1) * NST + n]     = acc[nt][1];
            Sp[(size_t)p * NST + n + 8]       = acc[nt][2];
            Sp[(size_t)(p + 1) * NST + n + 8] = acc[nt][3];
        }
    }
}

// yoff smem layout
#define YO_ACS 0
#define YO_CE  512
#define YO_SH  (YO_CE + 128 * 136 * 2)   // 35328
#define YO_SL  (YO_SH + 64 * 136 * 2)    // 52736
#define YO_SMEM (YO_SL + 64 * 136 * 2)   // 70144

__global__ __launch_bounds__(256) void yoff_tc(const float* __restrict__ Dv) {
    extern __shared__ __align__(16) char smc[];
    float* sAcs = (float*)(smc + YO_ACS);
    __half* sCe = (__half*)(smc + YO_CE);
    __half* sSh = (__half*)(smc + YO_SH);
    __half* sSl = (__half*)(smc + YO_SL);

    const int b = blockIdx.x;
    const int h = b & 31, c = (b >> 5) & 31, dir = b >> 10;
    const int tid = threadIdx.x;
    const int wid = tid >> 5, lane = tid & 31;
    const int m0 = wid * 16;
    const int ar = lane & 15, ac = (lane >> 4) * 8;
    const int g = lane >> 2, t4 = lane & 3;

    if (tid < CHK) sAcs[tid] = g_Acs[(b << 7) + tid];
    __syncthreads();

    // build Ce = C * exp(Acs[l]) row-major [l][n]
    {
        const int l = tid >> 1;
        const int n0 = (tid & 1) * 64;
        float e = __expf(sAcs[l]);
        const float* Cp = g_Cm + ((size_t)(dir * L + c * CHK) + l) * NST + n0;
        __half* crow = sCe + l * 136;
#pragma unroll 4
        for (int j = 0; j < 16; j++) {
            float4 v = *(const float4*)(Cp + j * 4);
            int n = n0 + j * 4;
            *(__half2*)(crow + n)     = __floats2half2_rn(v.x * e, v.y * e);
            *(__half2*)(crow + n + 2) = __floats2half2_rn(v.z * e, v.w * e);
        }
    }
    // build S hi/lo row-major [p][n] (matches global layout)
    {
        const int p = tid >> 2;
        const int n0 = (tid & 3) * 32;
        const float* Sp = g_states + ((size_t)b << 13) + (size_t)p * NST + n0;
        __half* shr = sSh + p * 136;
        __half* slr = sSl + p * 136;
#pragma unroll
        for (int j = 0; j < 8; j++) {
            float4 v = *(const float4*)(Sp + j * 4);
            int n = n0 + j * 4;
            __half h0, l0h, h1, l1h, h2, l2h, h3, l3h;
            split_hilo_h(v.x, h0, l0h); split_hilo_h(v.y, h1, l1h);
            split_hilo_h(v.z, h2, l2h); split_hilo_h(v.w, h3, l3h);
            *(__half2*)(shr + n)     = __halves2half2(h0, h1);
            *(__half2*)(shr + n + 2) = __halves2half2(h2, h3);
            *(__half2*)(slr + n)     = __halves2half2(l0h, l1h);
            *(__half2*)(slr + n + 2) = __halves2half2(l2h, l3h);
        }
    }
    __syncthreads();

    // Yoff[l][p] = Ce @ (Sh + Sl)
    float acc[8][4] = {};
#pragma unroll
    for (int kk = 0; kk < 8; kk++) {
        int k0 = kk * 16;
        uint32_t af[4];
        ldsm4(af, smem_u32(sCe + (m0 + ar) * 136 + k0 + ac));
        uint32_t bh[4][4], blo[4][4];
#pragma unroll
        for (int bt = 0; bt < 4; bt++) {
            ldsm4(bh[bt],  smem_u32(sSh + (bt * 16 + ar) * 136 + k0 + ac));
            ldsm4(blo[bt], smem_u32(sSl + (bt * 16 + ar) * 136 + k0 + ac));
        }
#pragma unroll
        for (int nt = 0; nt < 8; nt++) {
            int bt = nt >> 1, sel = nt & 1;
            mma16816h(acc[nt], af, bh[bt][sel], bh[bt][sel + 2]);
        }
#pragma unroll
        for (int nt = 0; nt < 8; nt++) {
            int bt = nt >> 1, sel = nt & 1;
            mma16816h(acc[nt], af, blo[bt][sel], blo[bt][sel + 2]);
        }
    }

    const float Dh = Dv[h];
    float* Yp = g_Yd + ((size_t)(dir * L + c * CHK)) * DIN + h * HD;
#pragma unroll
    for (int rr = 0; rr < 2; rr++) {
        int l = m0 + g + rr * 8;
        int tg = c * CHK + l;
        int ts = dir ? (L - 1 - tg) : tg;
        const float* xr = g_xc + (size_t)ts * CONVD + h * HD;
#pragma unroll
        for (int nt = 0; nt < 8; nt++) {
            int p = nt * 8 + t4 * 2;
            size_t o = (size_t)l * DIN + p;
            Yp[o]     += acc[nt][rr * 2]     + xr[p] * Dh;
            Yp[o + 1] += acc[nt][rr * 2 + 1] + xr[p + 1] * Dh;
        }
    }
}

// ---------------- inter-chunk recurrence (8-way split per (dir,h)) ----------------
__global__ void recur_kernel() {
    int bi = blockIdx.x;
    int seg = bi & 7, hh = bi >> 3;
    int dir = hh >> 5, h = hh & 31;
    int tid = threadIdx.x;
    float Hreg[4] = {0.f, 0.f, 0.f, 0.f};
    for (int c = 0; c < NC; c++) {
        int sb = (dir * NC + c) * NH + h;
        float dec = __expf(g_Acs[(sb << 7) + 127]);
        size_t base = ((size_t)sb << 13) + seg * 1024;
#pragma unroll
        for (int k = 0; k < 4; k++) {
            size_t off = base + tid + k * 256;
            float s = g_states[off];
            g_states[off] = Hreg[k];
            Hreg[k] = dec * Hreg[k] + s;
        }
    }
}

// ---------------- fd = x_og @ fc_D_w^T + D, tiled ----------------
__global__ __launch_bounds__(256) void fcD_kernel(const float* __restrict__ W,
                                                  const float* __restrict__ Dv) {
    int t0 = blockIdx.x * 32;
    __shared__ float sx[32][132];
    __shared__ float sW[32][132];
    int tid = threadIdx.x;
    int tx = tid & 15, ty = tid >> 4;
    float acc[2][2] = {};
    for (int kc = 0; kc < DIN; kc += 128) {
#pragma unroll
        for (int i = 0; i < 4; i++) {
            int u = tid + i * 256;
            int r = u >> 5, k4 = (u & 31) * 4;
            *(float4*)&sx[r][k4] = *(const float4*)(g_xc + (size_t)(t0 + r) * CONVD + kc + k4);
            *(float4*)&sW[r][k4] = *(const float4*)(W + (size_t)r * DIN + kc + k4);
        }
        __syncthreads();
#pragma unroll 8
        for (int k4 = 0; k4 < 128; k4 += 4) {
            float4 x0 = *(float4*)&sx[ty * 2][k4];
            float4 x1 = *(float4*)&sx[ty * 2 + 1][k4];
            float4 w0 = *(float4*)&sW[tx * 2][k4];
            float4 w1 = *(float4*)&sW[tx * 2 + 1][k4];
            acc[0][0] += x0.x * w0.x + x0.y * w0.y + x0.z * w0.z + x0.w * w0.w;
            acc[0][1] += x0.x * w1.x + x0.y * w1.y + x0.z * w1.z + x0.w * w1.w;
            acc[1][0] += x1.x * w0.x + x1.y * w0.y + x1.z * w0.z + x1.w * w0.w;
            acc[1][1] += x1.x * w1.x + x1.y * w1.y + x1.z * w1.z + x1.w * w1.w;
        }
        __syncthreads();
    }
#pragma unroll
    for (int i = 0; i < 2; i++)
#pragma unroll
        for (int j = 0; j < 2; j++)
            g_fd[(t0 + ty * 2 + i) * NH + tx * 2 + j] = acc[i][j] + Dv[tx * 2 + j];
}

// ---------------- shift + merge dirs + skip + gate + RMSNorm -> fp16 hi/lo ----------------
__global__ void combine_kernel(const float* __restrict__ norm_w) {
    int t = blockIdx.x;
    int tid = threadIdx.x;
    __shared__ float red[256];
    __shared__ float sc;
    float yg[8];
    float ss = 0.f;
#pragma unroll
    for (int k = 0; k < 8; k++) {
        int d = tid + k * 256;
        float yfw = (t > 0) ? g_Yd[((size_t)(t - 1)) * DIN + d] : 0.f;
        float ybw = (t < L - 1) ? g_Yd[((size_t)(L + (L - 2 - t))) * DIN + d] : 0.f;
        float x = g_xc[(size_t)t * CONVD + d];
        float fdv = g_fd[t * NH + (d >> 6)];
        float z = g_zx[(size_t)t * DPROJ + d];
        float v = (yfw + ybw + x * fdv) * (z * sigmoidf_(z));
        yg[k] = v;
        ss += v * v;
    }
    red[tid] = ss;
    __syncthreads();
    for (int o = 128; o > 0; o >>= 1) {
        if (tid < o) red[tid] += red[tid + o];
        __syncthreads();
    }
    if (tid == 0) sc = rsqrtf(red[0] * (1.f / DIN) + EPSV);
    __syncthreads();
    float s = sc;
#pragma unroll
    for (int k = 0; k < 8; k++) {
        int d = tid + k * 256;
        float v = yg[k] * s * norm_w[d];
        __half hv, lv;
        split_hilo_h(v, hv, lv);
        g_ynh[(size_t)t * DIN + d] = hv;
        g_ynl[(size_t)t * DIN + d] = lv;
    }
}

extern "C" void kernel_launch(void* const* d_in, const int* in_sizes, int n_in,
                              void* d_out, int out_size) {
    const float* u          = (const float*)d_in[0];
    const float* in_proj_w  = (const float*)d_in[1];
    const float* conv_w     = (const float*)d_in[2];
    const float* conv_b     = (const float*)d_in[3];
    const float* dt_bias    = (const float*)d_in[4];
    const float* A_log      = (const float*)d_in[5];
    const float* Dv         = (const float*)d_in[6];
    const float* fc_D_w     = (const float*)d_in[7];
    const float* norm_w     = (const float*)d_in[8];
    const float* out_proj_w = (const float*)d_in[9];
    float* out = (float*)d_out;

    float *zx, *Bm, *Cm, *G;
    __half *uh, *ul, *wi, *ynh, *ynl, *wo;
    cudaGetSymbolAddress((void**)&zx, g_zx);
    cudaGetSymbolAddress((void**)&Bm, g_Bm);
    cudaGetSymbolAddress((void**)&Cm, g_Cm);
    cudaGetSymbolAddress((void**)&G, g_G);
    cudaGetSymbolAddress((void**)&uh, g_uh);
    cudaGetSymbolAddress((void**)&ul, g_ul);
    cudaGetSymbolAddress((void**)&wi, g_wi);
    cudaGetSymbolAddress((void**)&ynh, g_ynh);
    cudaGetSymbolAddress((void**)&ynl, g_ynl);
    cudaGetSymbolAddress((void**)&wo, g_wo);

    const int smemB = 2 * 3 * 128 * APAD * 2;  // 61440 B
    cudaFuncSetAttribute(gemm_2t, cudaFuncAttributeMaxDynamicSharedMemorySize, smemB);
    cudaFuncSetAttribute(ydiag_states_tc, cudaFuncAttributeMaxDynamicSharedMemorySize, YD_SMEM);
    cudaFuncSetAttribute(yoff_tc, cudaFuncAttributeMaxDynamicSharedMemorySize, YO_SMEM);

    // 0) convert
    cvt_hilo_kernel<<<((size_t)L * DM + 255) / 256, 256>>>(u, uh, ul, (size_t)L * DM);
    cvt_h_kernel<<<((size_t)DPROJ * DM + 255) / 256, 256>>>(in_proj_w, wi, (size_t)DPROJ * DM);
    cvt_h_kernel<<<((size_t)DM * DIN + 255) / 256, 256>>>(out_proj_w, wo, (size_t)DM * DIN);

    // 1) in_proj
    gemm_2t<<<dim3((DPROJ + 127) / 128, L / 128), 256, smemB>>>(uh, ul, wi, zx, DPROJ, DM);
    // 2) conv + silu
    conv_kernel<<<((size_t)L * CONVD + 255) / 256, 256>>>(conv_w, conv_b);
    // 3) dt softplus
    dt_kernel<<<(2 * L * NH + 255) / 256, 256>>>(dt_bias);
    // 4) B/C prep
    prep_bc_kernel<<<(2 * L * NST + 255) / 256, 256>>>();
    // 5) per-chunk cumsum of A*dt
    acs_kernel<<<dim3(NC, 2), 32>>>(A_log);
    // 6) G = C B^T
    sgemm64_nt<<<dim3(2, 2, 2 * NC), 256>>>(Cm, Bm, G);
    // 7) Y_diag + chunk states (tensor cores)
    ydiag_states_tc<<<2 * NC * NH, 256, YD_SMEM>>>();
    // 8) inter-chunk recurrence
    recur_kernel<<<512, 256>>>();
    // 9) Y_off + x*D (tensor cores)
    yoff_tc<<<2 * NC * NH, 256, YO_SMEM>>>(Dv);
    // 10) fd
    fcD_kernel<<<L / 32, 256>>>(fc_D_w, Dv);
    // 11) shift/merge/gate/RMSNorm
    combine_kernel<<<L, 256>>>(norm_w);
    // 12) out_proj
    gemm_2t<<<dim3(DM / 128, L / 128), 256, smemB>>>(ynh, ynl, wo, out, DM, DIN);
}

// round 14
// speedup vs baseline: 1.1251x; 1.1251x over previous
#include <cuda_runtime.h>
#include <cuda_bf16.h>
#include <cuda_fp16.h>
#include <math.h>
#include <stdint.h>

#define L 4096
#define DM 1024
#define DIN 2048
#define NH 32
#define HD 64
#define NST 128
#define CONVD 2560
#define DPROJ 4672
#define CHK 128
#define NC 32
#define EPSV 1e-5f

// ---------------- scratch (static device globals; no allocation) ----------------
__device__ float g_zx[(size_t)L * DPROJ];
__device__ float g_xc[(size_t)L * CONVD];
__device__ float g_dt2[2 * L * NH];
__device__ float g_Bm[(size_t)2 * L * NST];
__device__ float g_Cm[(size_t)2 * L * NST];
__device__ float g_Acs[2 * NC * NH * CHK];
__device__ float g_G[(size_t)2 * NC * CHK * CHK];
__device__ float g_Yd[(size_t)2 * L * DIN];
__device__ float g_states[(size_t)2 * NC * NH * HD * NST];
__device__ float g_fd[L * NH];

__device__ __align__(16) __half g_uh[(size_t)L * DM];
__device__ __align__(16) __half g_ul[(size_t)L * DM];
__device__ __align__(16) __half g_wi[(size_t)DPROJ * DM];
__device__ __align__(16) __half g_ynh[(size_t)L * DIN];
__device__ __align__(16) __half g_ynl[(size_t)L * DIN];
__device__ __align__(16) __half g_wo[(size_t)DM * DIN];

__device__ __forceinline__ float sigmoidf_(float x) { return 1.f / (1.f + __expf(-x)); }

__device__ __forceinline__ uint32_t smem_u32(const void* p) {
    uint32_t a;
    asm("{ .reg .u64 tmp; cvta.to.shared.u64 tmp, %1; cvt.u32.u64 %0, tmp; }" : "=r"(a) : "l"(p));
    return a;
}
__device__ __forceinline__ void cp_async16(uint32_t dst, const void* src, int srcsize) {
    asm volatile("cp.async.cg.shared.global [%0], [%1], 16, %2;"
                 :: "r"(dst), "l"(src), "r"(srcsize));
}
#define CP_COMMIT() asm volatile("cp.async.commit_group;" ::: "memory")
#define CP_WAIT1()  asm volatile("cp.async.wait_group 1;"  ::: "memory")
#define CP_WAIT0()  asm volatile("cp.async.wait_group 0;"  ::: "memory")

__device__ __forceinline__ void ldsm4(uint32_t* r, uint32_t addr) {
    asm volatile("ldmatrix.sync.aligned.m8n8.x4.shared.b16 {%0,%1,%2,%3}, [%4];"
                 : "=r"(r[0]), "=r"(r[1]), "=r"(r[2]), "=r"(r[3]) : "r"(addr));
}
__device__ __forceinline__ void mma16816h(float* c, const uint32_t* a, uint32_t b0, uint32_t b1) {
    asm volatile("mma.sync.aligned.m16n8k16.row.col.f32.f16.f16.f32 "
                 "{%0,%1,%2,%3}, {%4,%5,%6,%7}, {%8,%9}, {%0,%1,%2,%3};"
                 : "+f"(c[0]), "+f"(c[1]), "+f"(c[2]), "+f"(c[3])
                 : "r"(a[0]), "r"(a[1]), "r"(a[2]), "r"(a[3]), "r"(b0), "r"(b1));
}
__device__ __forceinline__ void split_hilo_h(float v, __half& h, __half& l) {
    h = __float2half(v);
    l = __float2half(v - __half2float(h));
}

// ---- packed f32x2 FMA (Blackwell FFMA2; only reachable via PTX) ----
__device__ __forceinline__ void fma2(unsigned long long& acc,
                                     unsigned long long a, unsigned long long b) {
    asm("fma.rn.f32x2 %0, %1, %2, %0;" : "+l"(acc) : "l"(a), "l"(b));
}
__device__ __forceinline__ unsigned long long pk2(float a, float b) {
    unsigned long long r;
    asm("mov.b64 %0, {%1, %2};" : "=l"(r) : "f"(a), "f"(b));
    return r;
}
__device__ __forceinline__ void upk2(unsigned long long v, float& a, float& b) {
    asm("mov.b64 {%0, %1}, %2;" : "=f"(a), "=f"(b) : "l"(v));
}

// ---------------- fp32 -> fp16 hi/lo split ----------------
__global__ void cvt_hilo_kernel(const float* __restrict__ x,
                                __half* __restrict__ hi,
                                __half* __restrict__ lo, size_t n) {
    size_t i = (size_t)blockIdx.x * blockDim.x + threadIdx.x;
    if (i >= n) return;
    __half h, lv;
    split_hilo_h(x[i], h, lv);
    hi[i] = h; lo[i] = lv;
}
__global__ void cvt_h_kernel(const float* __restrict__ x, __half* __restrict__ o, size_t n) {
    size_t i = (size_t)blockIdx.x * blockDim.x + threadIdx.x;
    if (i >= n) return;
    o[i] = __float2half(x[i]);
}

// ===== mma.sync fp16 2-term GEMM, 2-stage cp.async pipeline (proven) =====
#define KC 32
#define APAD 40

__global__ __launch_bounds__(256, 2) void gemm_2t(
    const __half* __restrict__ Ah, const __half* __restrict__ Al,
    const __half* __restrict__ Bw,
    float* __restrict__ Cc, int Ntot, int Ktot) {
    extern __shared__ __align__(16) __half sm[];
    const int tid = threadIdx.x;
    const int bRow = blockIdx.y * 128, bCol = blockIdx.x * 128;
    const int wid = tid >> 5, lane = tid & 31;
    const int wm = (wid >> 2) * 64, wn = (wid & 3) * 32;

    __half* sp[2][3];
#pragma unroll
    for (int s = 0; s < 2; s++)
#pragma unroll
        for (int o = 0; o < 3; o++) sp[s][o] = sm + ((s * 3 + o) * 128 * APAD);

    float acc[4][4][4];
#pragma unroll
    for (int i = 0; i < 4; i++)
#pragma unroll
        for (int j = 0; j < 4; j++)
#pragma unroll
            for (int q = 0; q < 4; q++) acc[i][j][q] = 0.f;

    const int nst = Ktot / KC;

    auto issue = [&](int s, int c) {
        int kt = c * KC;
#pragma unroll
        for (int i = 0; i < 2; i++) {
            int u = tid + i * 256;
            int r = u >> 2, kc = (u & 3) * 8;
            size_t ga = (size_t)(bRow + r) * Ktot + kt + kc;
            cp_async16(smem_u32(sp[s][0] + r * APAD + kc), Ah + ga, 16);
            cp_async16(smem_u32(sp[s][1] + r * APAD + kc), Al + ga, 16);
            int ok = (bCol + r) < Ntot ? 16 : 0;
            size_t gb = ok ? ((size_t)(bCol + r) * Ktot + kt + kc) : 0;
            cp_async16(smem_u32(sp[s][2] + r * APAD + kc), Bw + gb, ok);
        }
    };

    issue(0, 0);
    CP_COMMIT();

    const int ar = lane & 15, ac = (lane >> 4) * 8;
    for (int c = 0; c < nst; c++) {
        if (c + 1 < nst) { issue((c + 1) & 1, c + 1); CP_COMMIT(); CP_WAIT1(); }
        else CP_WAIT0();
        __syncthreads();
        const __half* sa_h = sp[c & 1][0];
        const __half* sa_l = sp[c & 1][1];
        const __half* sb   = sp[c & 1][2];
#pragma unroll
        for (int kk = 0; kk < 2; kk++) {
            int k0 = kk * 16;
            uint32_t bf[2][4];
#pragma unroll
            for (int bt = 0; bt < 2; bt++)
                ldsm4(bf[bt], smem_u32(sb + (wn + bt * 16 + ar) * APAD + k0 + ac));
#pragma unroll
            for (int mt = 0; mt < 4; mt++) {
                uint32_t afh[4], afl[4];
                ldsm4(afh, smem_u32(sa_h + (wm + mt * 16 + ar) * APAD + k0 + ac));
                ldsm4(afl, smem_u32(sa_l + (wm + mt * 16 + ar) * APAD + k0 + ac));
#pragma unroll
                for (int nt = 0; nt < 4; nt++) {
                    int bt = nt >> 1, sel = nt & 1;
                    mma16816h(acc[mt][nt], afh, bf[bt][sel], bf[bt][sel + 2]);
                }
#pragma unroll
                for (int nt = 0; nt < 4; nt++) {
                    int bt = nt >> 1, sel = nt & 1;
                    mma16816h(acc[mt][nt], afl, bf[bt][sel], bf[bt][sel + 2]);
                }
            }
        }
        __syncthreads();
    }

    const int g = lane >> 2, t4 = lane & 3;
#pragma unroll
    for (int mt = 0; mt < 4; mt++) {
#pragma unroll
        for (int nt = 0; nt < 4; nt++) {
            int row = bRow + wm + mt * 16 + g;
            int col = bCol + wn + nt * 8 + t4 * 2;
            if (col < Ntot) {
                float* p0 = Cc + (size_t)row * Ntot + col;
                p0[0] = acc[mt][nt][0];
                p0[1] = acc[mt][nt][1];
                float* p1 = p0 + (size_t)8 * Ntot;
                p1[0] = acc[mt][nt][2];
                p1[1] = acc[mt][nt][3];
            }
        }
    }
}

// ---------------- 64x64-tile batched NT SGEMM for G = C B^T ----------------
__global__ __launch_bounds__(256) void sgemm64_nt(const float* __restrict__ A,
                                                  const float* __restrict__ B,
                                                  float* __restrict__ C) {
    A += (size_t)blockIdx.z * CHK * NST;
    B += (size_t)blockIdx.z * CHK * NST;
    C += (size_t)blockIdx.z * CHK * CHK;
    __shared__ float As[16][68];
    __shared__ float Bs[16][68];
    int tid = threadIdx.x;
    int bRow = blockIdx.y * 64, bCol = blockIdx.x * 64;
    int tx = tid & 15, ty = tid >> 4;
    float acc[4][4] = {};
    int lr = tid >> 2, lk = (tid & 3) * 4;
    for (int kt = 0; kt < NST; kt += 16) {
        {
            float4 v = *(const float4*)(A + (size_t)(bRow + lr) * NST + kt + lk);
            As[lk][lr] = v.x; As[lk + 1][lr] = v.y; As[lk + 2][lr] = v.z; As[lk + 3][lr] = v.w;
            float4 w = *(const float4*)(B + (size_t)(bCol + lr) * NST + kt + lk);
            Bs[lk][lr] = w.x; Bs[lk + 1][lr] = w.y; Bs[lk + 2][lr] = w.z; Bs[lk + 3][lr] = w.w;
        }
        __syncthreads();
#pragma unroll
        for (int k = 0; k < 16; k++) {
            float4 ra = *(const float4*)&As[k][ty * 4];
            float4 rb = *(const float4*)&Bs[k][tx * 4];
            float a0 = ra.x, a1 = ra.y, a2 = ra.z, a3 = ra.w;
            acc[0][0] += a0 * rb.x; acc[0][1] += a0 * rb.y; acc[0][2] += a0 * rb.z; acc[0][3] += a0 * rb.w;
            acc[1][0] += a1 * rb.x; acc[1][1] += a1 * rb.y; acc[1][2] += a1 * rb.z; acc[1][3] += a1 * rb.w;
            acc[2][0] += a2 * rb.x; acc[2][1] += a2 * rb.y; acc[2][2] += a2 * rb.z; acc[2][3] += a2 * rb.w;
            acc[3][0] += a3 * rb.x; acc[3][1] += a3 * rb.y; acc[3][2] += a3 * rb.z; acc[3][3] += a3 * rb.w;
        }
        __syncthreads();
    }
#pragma unroll
    for (int i = 0; i < 4; i++) {
        float* p = C + (size_t)(bRow + ty * 4 + i) * CHK + bCol + tx * 4;
        p[0] = acc[i][0]; p[1] = acc[i][1]; p[2] = acc[i][2]; p[3] = acc[i][3];
    }
}

// ---------------- depthwise causal conv (k=4) + bias + silu ----------------
__global__ void conv_kernel(const float* __restrict__ cw, const float* __restrict__ cb) {
    size_t idx = (size_t)blockIdx.x * blockDim.x + threadIdx.x;
    if (idx >= (size_t)L * CONVD) return;
    int c = (int)(idx % CONVD);
    int t = (int)(idx / CONVD);
    float acc = cb[c];
#pragma unroll
    for (int k = 0; k < 4; k++) {
        int ts = t - 3 + k;
        if (ts >= 0) acc += cw[c * 4 + k] * g_zx[(size_t)ts * DPROJ + DIN + c];
    }
    g_xc[idx] = acc * sigmoidf_(acc);
}

// ---------------- dt (with direction flip) + softplus ----------------
__global__ void dt_kernel(const float* __restrict__ dt_bias) {
    int idx = blockIdx.x * blockDim.x + threadIdx.x;
    if (idx >= 2 * L * NH) return;
    int h = idx & 31;
    int t = (idx >> 5) & (L - 1);
    int dir = idx >> 17;
    int ts = dir ? (L - 1 - t) : t;
    float v = g_zx[(size_t)ts * DPROJ + DIN + CONVD + dir * NH + h] + dt_bias[h];
    g_dt2[idx] = (v > 20.f) ? v : log1pf(expf(v));
}

// ---------------- B/C split per direction (flip for dir1) ----------------
__global__ void prep_bc_kernel() {
    int idx = blockIdx.x * blockDim.x + threadIdx.x;
    if (idx >= 2 * L * NST) return;
    int n = idx & 127;
    int t = (idx >> 7) & (L - 1);
    int dir = idx >> 19;
    int ts = dir ? (L - 1 - t) : t;
    int off = dir ? 256 : 0;
    const float* p = g_xc + (size_t)ts * CONVD + DIN + off;
    g_Bm[idx] = p[n];
    g_Cm[idx] = p[NST + n];
}

// ---------------- per-chunk cumsum of A*dt ----------------
__global__ void acs_kernel(const float* __restrict__ A_log) {
    int c = blockIdx.x, dir = blockIdx.y, h = threadIdx.x;
    float Ah = -expf(A_log[h]);
    float cum = 0.f;
    float* out = g_Acs + (((dir * NC + c) * NH + h) << 7);
    const float* dtp = g_dt2 + ((size_t)(dir * L + c * CHK)) * NH + h;
    for (int l = 0; l < CHK; l++) {
        cum += Ah * dtp[l * NH];
        out[l] = cum;
    }
}

// ---------------- per (dir,chunk,head): Y_diag = (G.*Lmat)@xdt ; states = B^T @ (decay.*xdt) ----
// vectorized smem + packed f32x2 FMA inner loops
__global__ __launch_bounds__(256) void ydiag_states_kernel() {
    int b = blockIdx.x;
    int h = b & 31, c = (b >> 5) & 31, dir = b >> 10;
    int tid = threadIdx.x;
    __shared__ float sAcs[CHK];
    __shared__ float sDt[CHK];
    __shared__ float sCv[CHK];
    __shared__ float sR[CHK][8];
    __shared__ __align__(16) float sMlT[16][132];   // [s_in_slab][l]
    __shared__ __align__(16) float sXs[16][68];     // [k][p]
    __shared__ __align__(16) float sB[16][132];     // [k][n]
    __shared__ __align__(16) float sXd[16][68];     // [k][p]
    if (tid < CHK) {
        sAcs[tid] = g_Acs[(b << 7) + tid];
        sDt[tid] = g_dt2[((size_t)(dir * L + c * CHK + tid)) * NH + h];
    }
    __syncthreads();
    if (tid < CHK) sCv[tid] = __expf(sAcs[tid | 15] - sAcs[tid]);
    {
        int i0 = tid * 4;
#pragma unroll
        for (int q = 0; q < 4; q++) {
            int idx = i0 + q;
            int l = idx >> 3, st = idx & 7;
            sR[l][st] = __expf(fminf(sAcs[l] - sAcs[st * 16 + 15], 85.f));
        }
    }
    __syncthreads();
    const float* Gp = g_G + ((size_t)(dir * NC + c) << 14);
    int tx = tid & 15, ty = tid >> 4;
    unsigned long long accp[8][2] = {};
    int l0 = tid >> 1, skb = (tid & 1) * 8;
    for (int st = 0; st < 8; st++) {
        {
            float r = sR[l0][st];
#pragma unroll
            for (int i = 0; i < 8; i++) {
                int s = st * 16 + skb + i;
                float g = Gp[l0 * CHK + s];
                sMlT[skb + i][l0] = (l0 >= s) ? g * r * sCv[s] : 0.f;
            }
        }
        {
            int sk = tid >> 4, p0 = (tid & 15) * 4;
            int l = st * 16 + sk;
            int tg = c * CHK + l;
            int ts = dir ? (L - 1 - tg) : tg;
            float dtv = sDt[l];
            float4 v = *(const float4*)(g_xc + (size_t)ts * CONVD + h * HD + p0);
            sXs[sk][p0] = v.x * dtv; sXs[sk][p0 + 1] = v.y * dtv;
            sXs[sk][p0 + 2] = v.z * dtv; sXs[sk][p0 + 3] = v.w * dtv;
        }
        __syncthreads();
#pragma unroll
        for (int sk = 0; sk < 16; sk++) {
            unsigned long long xp0 = *(const unsigned long long*)&sXs[sk][tx * 4];
            unsigned long long xp1 = *(const unsigned long long*)&sXs[sk][tx * 4 + 2];
            float4 m0 = *(const float4*)&sMlT[sk][ty * 8];
            float4 m1 = *(const float4*)&sMlT[sk][ty * 8 + 4];
            float mm[8] = {m0.x, m0.y, m0.z, m0.w, m1.x, m1.y, m1.z, m1.w};
#pragma unroll
            for (int i = 0; i < 8; i++) {
                unsigned long long mp = pk2(mm[i], mm[i]);
                fma2(accp[i][0], mp, xp0);
                fma2(accp[i][1], mp, xp1);
            }
        }
        __syncthreads();
    }
    float* Yp = g_Yd + ((size_t)(dir * L + c * CHK)) * DIN + h * HD;
#pragma unroll
    for (int i = 0; i < 8; i++) {
        float a0, a1, a2, a3;
        upk2(accp[i][0], a0, a1);
        upk2(accp[i][1], a2, a3);
        float* p = Yp + (size_t)(ty * 8 + i) * DIN + tx * 4;
        p[0] = a0; p[1] = a1; p[2] = a2; p[3] = a3;
    }

    // ---- states ----
    unsigned long long accSp[8][2] = {};
    int n0 = (tid & 31) * 4;
    int p0s = (tid >> 5) * 8;
    float lastA = sAcs[127];
    const float* Bp = g_Bm + ((size_t)(dir * L + c * CHK)) * NST;
    for (int lt = 0; lt < 8; lt++) {
        {
            int lk = tid >> 4, nb = (tid & 15) * 8;
            float4 v0 = *(const float4*)(Bp + (size_t)(lt * 16 + lk) * NST + nb);
            float4 v1 = *(const float4*)(Bp + (size_t)(lt * 16 + lk) * NST + nb + 4);
            sB[lk][nb] = v0.x; sB[lk][nb + 1] = v0.y; sB[lk][nb + 2] = v0.z; sB[lk][nb + 3] = v0.w;
            sB[lk][nb + 4] = v1.x; sB[lk][nb + 5] = v1.y; sB[lk][nb + 6] = v1.z; sB[lk][nb + 7] = v1.w;
            int pb = (tid & 15) * 4;
            int l = lt * 16 + lk;
            int tg = c * CHK + l;
            int ts = dir ? (L - 1 - tg) : tg;
            float dec = __expf(lastA - sAcs[l]) * sDt[l];
            float4 xv = *(const float4*)(g_xc + (size_t)ts * CONVD + h * HD + pb);
            sXd[lk][pb] = xv.x * dec; sXd[lk][pb + 1] = xv.y * dec;
            sXd[lk][pb + 2] = xv.z * dec; sXd[lk][pb + 3] = xv.w * dec;
        }
        __syncthreads();
#pragma unroll
        for (int lk2 = 0; lk2 < 16; lk2++) {
            float4 p0v = *(const float4*)&sXd[lk2][p0s];
            float4 p1v = *(const float4*)&sXd[lk2][p0s + 4];
            float pv[8] = {p0v.x, p0v.y, p0v.z, p0v.w, p1v.x, p1v.y, p1v.z, p1v.w};
            unsigned long long np0 = *(const unsigned long long*)&sB[lk2][n0];
            unsigned long long np1 = *(const unsigned long long*)&sB[lk2][n0 + 2];
#pragma unroll
            for (int i = 0; i < 8; i++) {
                unsigned long long pp = pk2(pv[i], pv[i]);
                fma2(accSp[i][0], pp, np0);
                fma2(accSp[i][1], pp, np1);
            }
        }
        __syncthreads();
    }
    float* Sp = g_states + ((size_t)b << 13);
#pragma unroll
    for (int i = 0; i < 8; i++) {
        float a0, a1, a2, a3;
        upk2(accSp[i][0], a0, a1);
        upk2(accSp[i][1], a2, a3);
        float* p = Sp + (size_t)(p0s + i) * NST + n0;
        p[0] = a0; p[1] = a1; p[2] = a2; p[3] = a3;
    }
}

// ---------------- inter-chunk recurrence (8-way split per (dir,h)) ----------------
__global__ void recur_kernel() {
    int bi = blockIdx.x;
    int seg = bi & 7, hh = bi >> 3;
    int dir = hh >> 5, h = hh & 31;
    int tid = threadIdx.x;
    float Hreg[4] = {0.f, 0.f, 0.f, 0.f};
    for (int c = 0; c < NC; c++) {
        int sb = (dir * NC + c) * NH + h;
        float dec = __expf(g_Acs[(sb << 7) + 127]);
        size_t base = ((size_t)sb << 13) + seg * 1024;
#pragma unroll
        for (int k = 0; k < 4; k++) {
            size_t off = base + tid + k * 256;
            float s = g_states[off];
            g_states[off] = Hreg[k];
            Hreg[k] = dec * Hreg[k] + s;
        }
    }
}

// ---------------- Y_off = exp(Acs[l]) * C @ state^T ; Yd += Y_off + x*D ----------------
// vectorized smem + packed f32x2 FMA
__global__ __launch_bounds__(256) void yoff_kernel(const float* __restrict__ Dv) {
    int b = blockIdx.x;
    int h = b & 31, c = (b >> 5) & 31, dir = b >> 10;
    int tid = threadIdx.x;
    __shared__ float sAcs[CHK];
    __shared__ __align__(16) float sCT[16][132];   // [n_in_slab][l]
    __shared__ __align__(16) float sST[16][68];    // [n_in_slab][p]
    if (tid < CHK) sAcs[tid] = g_Acs[(b << 7) + tid];
    __syncthreads();
    const float* Cp = g_Cm + ((size_t)(dir * L + c * CHK)) * NST;
    const float* Sp = g_states + ((size_t)b << 13);
    int tx = tid & 15, ty = tid >> 4;
    unsigned long long accp[8][2] = {};
    int l0 = tid >> 1, nkb = (tid & 1) * 8;
    int p1 = tid >> 2, nkb2 = (tid & 3) * 4;
    for (int nt = 0; nt < 8; nt++) {
#pragma unroll
        for (int i = 0; i < 8; i++)
            sCT[nkb + i][l0] = Cp[(size_t)l0 * NST + nt * 16 + nkb + i];
        {
            float4 v = *(const float4*)(Sp + (size_t)p1 * NST + nt * 16 + nkb2);
            sST[nkb2][p1] = v.x; sST[nkb2 + 1][p1] = v.y;
            sST[nkb2 + 2][p1] = v.z; sST[nkb2 + 3][p1] = v.w;
        }
        __syncthreads();
#pragma unroll
        for (int nk = 0; nk < 16; nk++) {
            unsigned long long sp0 = *(const unsigned long long*)&sST[nk][tx * 4];
            unsigned long long sp1 = *(const unsigned long long*)&sST[nk][tx * 4 + 2];
            float4 c0 = *(const float4*)&sCT[nk][ty * 8];
            float4 c1 = *(const float4*)&sCT[nk][ty * 8 + 4];
            float cv[8] = {c0.x, c0.y, c0.z, c0.w, c1.x, c1.y, c1.z, c1.w};
#pragma unroll
            for (int i = 0; i < 8; i++) {
                unsigned long long cp = pk2(cv[i], cv[i]);
                fma2(accp[i][0], cp, sp0);
                fma2(accp[i][1], cp, sp1);
            }
        }
        __syncthreads();
    }
    float Dh = Dv[h];
    float* Yp = g_Yd + ((size_t)(dir * L + c * CHK)) * DIN + h * HD;
#pragma unroll
    for (int i = 0; i < 8; i++) {
        int l = ty * 8 + i;
        float e = __expf(sAcs[l]);
        int tglob = c * CHK + l;
        int ts = dir ? (L - 1 - tglob) : tglob;
        const float* xrow = g_xc + (size_t)ts * CONVD + h * HD;
        float a0, a1, a2, a3;
        upk2(accp[i][0], a0, a1);
        upk2(accp[i][1], a2, a3);
        float av[4] = {a0, a1, a2, a3};
#pragma unroll
        for (int j = 0; j < 4; j++) {
            int p = tx * 4 + j;
            size_t o = (size_t)l * DIN + p;
            Yp[o] = Yp[o] + e * av[j] + xrow[p] * Dh;
        }
    }
}

// ---------------- fd = x_og @ fc_D_w^T + D, tiled (32 t-rows per block) ----------------
__global__ __launch_bounds__(256) void fcD_kernel(const float* __restrict__ W,
                                                  const float* __restrict__ Dv) {
    int t0 = blockIdx.x * 32;
    __shared__ float sx[32][132];
    __shared__ float sW[32][132];
    int tid = threadIdx.x;
    int tx = tid & 15, ty = tid >> 4;
    float acc[2][2] = {};
    for (int kc = 0; kc < DIN; kc += 128) {
#pragma unroll
        for (int i = 0; i < 4; i++) {
            int u = tid + i * 256;
            int r = u >> 5, k4 = (u & 31) * 4;
            *(float4*)&sx[r][k4] = *(const float4*)(g_xc + (size_t)(t0 + r) * CONVD + kc + k4);
            *(float4*)&sW[r][k4] = *(const float4*)(W + (size_t)r * DIN + kc + k4);
        }
        __syncthreads();
#pragma unroll 8
        for (int k4 = 0; k4 < 128; k4 += 4) {
            float4 x0 = *(float4*)&sx[ty * 2][k4];
            float4 x1 = *(float4*)&sx[ty * 2 + 1][k4];
            float4 w0 = *(float4*)&sW[tx * 2][k4];
            float4 w1 = *(float4*)&sW[tx * 2 + 1][k4];
            acc[0][0] += x0.x * w0.x + x0.y * w0.y + x0.z * w0.z + x0.w * w0.w;
            acc[0][1] += x0.x * w1.x + x0.y * w1.y + x0.z * w1.z + x0.w * w1.w;
            acc[1][0] += x1.x * w0.x + x1.y * w0.y + x1.z * w0.z + x1.w * w0.w;
            acc[1][1] += x1.x * w1.x + x1.y * w1.y + x1.z * w1.z + x1.w * w1.w;
        }
        __syncthreads();
    }
#pragma unroll
    for (int i = 0; i < 2; i++)
#pragma unroll
        for (int j = 0; j < 2; j++)
            g_fd[(t0 + ty * 2 + i) * NH + tx * 2 + j] = acc[i][j] + Dv[tx * 2 + j];
}

// ---------------- shift + merge dirs + skip + gate + RMSNorm -> fp16 hi/lo ----------------
__global__ void combine_kernel(const float* __restrict__ norm_w) {
    int t = blockIdx.x;
    int tid = threadIdx.x;
    __shared__ float red[256];
    __shared__ float sc;
    float yg[8];
    float ss = 0.f;
#pragma unroll
    for (int k = 0; k < 8; k++) {
        int d = tid + k * 256;
        float yfw = (t > 0) ? g_Yd[((size_t)(t - 1)) * DIN + d] : 0.f;
        float ybw = (t < L - 1) ? g_Yd[((size_t)(L + (L - 2 - t))) * DIN + d] : 0.f;
        float x = g_xc[(size_t)t * CONVD + d];
        float fdv = g_fd[t * NH + (d >> 6)];
        float z = g_zx[(size_t)t * DPROJ + d];
        float v = (yfw + ybw + x * fdv) * (z * sigmoidf_(z));
        yg[k] = v;
        ss += v * v;
    }
    red[tid] = ss;
    __syncthreads();
    for (int o = 128; o > 0; o >>= 1) {
        if (tid < o) red[tid] += red[tid + o];
        __syncthreads();
    }
    if (tid == 0) sc = rsqrtf(red[0] * (1.f / DIN) + EPSV);
    __syncthreads();
    float s = sc;
#pragma unroll
    for (int k = 0; k < 8; k++) {
        int d = tid + k * 256;
        float v = yg[k] * s * norm_w[d];
        __half hv, lv;
        split_hilo_h(v, hv, lv);
        g_ynh[(size_t)t * DIN + d] = hv;
        g_ynl[(size_t)t * DIN + d] = lv;
    }
}

extern "C" void kernel_launch(void* const* d_in, const int* in_sizes, int n_in,
                              void* d_out, int out_size) {
    const float* u          = (const float*)d_in[0];
    const float* in_proj_w  = (const float*)d_in[1];
    const float* conv_w     = (const float*)d_in[2];
    const float* conv_b     = (const float*)d_in[3];
    const float* dt_bias    = (const float*)d_in[4];
    const float* A_log      = (const float*)d_in[5];
    const float* Dv         = (const float*)d_in[6];
    const float* fc_D_w     = (const float*)d_in[7];
    const float* norm_w     = (const float*)d_in[8];
    const float* out_proj_w = (const float*)d_in[9];
    float* out = (float*)d_out;

    float *zx, *Bm, *Cm, *G;
    __half *uh, *ul, *wi, *ynh, *ynl, *wo;
    cudaGetSymbolAddress((void**)&zx, g_zx);
    cudaGetSymbolAddress((void**)&Bm, g_Bm);
    cudaGetSymbolAddress((void**)&Cm, g_Cm);
    cudaGetSymbolAddress((void**)&G, g_G);
    cudaGetSymbolAddress((void**)&uh, g_uh);
    cudaGetSymbolAddress((void**)&ul, g_ul);
    cudaGetSymbolAddress((void**)&wi, g_wi);
    cudaGetSymbolAddress((void**)&ynh, g_ynh);
    cudaGetSymbolAddress((void**)&ynl, g_ynl);
    cudaGetSymbolAddress((void**)&wo, g_wo);

    const int smemB = 2 * 3 * 128 * APAD * 2;  // 61440 B
    cudaFuncSetAttribute(gemm_2t, cudaFuncAttributeMaxDynamicSharedMemorySize, smemB);

    // 0) convert: activations fp16 hi/lo, weights single fp16
    cvt_hilo_kernel<<<((size_t)L * DM + 255) / 256, 256>>>(u, uh, ul, (size_t)L * DM);
    cvt_h_kernel<<<((size_t)DPROJ * DM + 255) / 256, 256>>>(in_proj_w, wi, (size_t)DPROJ * DM);
    cvt_h_kernel<<<((size_t)DM * DIN + 255) / 256, 256>>>(out_proj_w, wo, (size_t)DM * DIN);

    // 1) in_proj
    gemm_2t<<<dim3((DPROJ + 127) / 128, L / 128), 256, smemB>>>(uh, ul, wi, zx, DPROJ, DM);
    // 2) conv + silu
    conv_kernel<<<((size_t)L * CONVD + 255) / 256, 256>>>(conv_w, conv_b);
    // 3) dt softplus
    dt_kernel<<<(2 * L * NH + 255) / 256, 256>>>(dt_bias);
    // 4) B/C prep
    prep_bc_kernel<<<(2 * L * NST + 255) / 256, 256>>>();
    // 5) per-chunk cumsum of A*dt
    acs_kernel<<<dim3(NC, 2), 32>>>(A_log);
    // 6) G = C B^T per (dir,chunk), 64x64 tiles
    sgemm64_nt<<<dim3(2, 2, 2 * NC), 256>>>(Cm, Bm, G);
    // 7) Y_diag + chunk states (f32x2 packed FMA)
    ydiag_states_kernel<<<2 * NC * NH, 256>>>();
    // 8) inter-chunk recurrence
    recur_kernel<<<512, 256>>>();
    // 9) Y_off + x*D (f32x2 packed FMA)
    yoff_kernel<<<2 * NC * NH, 256>>>(Dv);
    // 10) fd
    fcD_kernel<<<L / 32, 256>>>(fc_D_w, Dv);
    // 11) shift/merge/gate/RMSNorm
    combine_kernel<<<L, 256>>>(norm_w);
    // 12) out_proj
    gemm_2t<<<dim3(DM / 128, L / 128), 256, smemB>>>(ynh, ynl, wo, out, DM, DIN);
}

// round 16
// speedup vs baseline: 1.3250x; 1.1776x over previous
#include <cuda_runtime.h>
#include <cuda_bf16.h>
#include <cuda_fp16.h>
#include <math.h>
#include <stdint.h>

#define L 4096
#define DM 1024
#define DIN 2048
#define NH 32
#define HD 64
#define NST 128
#define CONVD 2560
#define DPROJ 4672
#define CHK 128
#define NC 32
#define EPSV 1e-5f

// ---------------- scratch (static device globals; no allocation) ----------------
__device__ float g_zx[(size_t)L * DPROJ];
__device__ float g_xc[(size_t)L * CONVD];
__device__ float g_dt2[2 * L * NH];
__device__ float g_Bm[(size_t)2 * L * NST];
__device__ float g_Cm[(size_t)2 * L * NST];
__device__ float g_Acs[2 * NC * NH * CHK];
__device__ float g_G[(size_t)2 * NC * CHK * CHK];
__device__ float g_Yd[(size_t)2 * L * DIN];
__device__ float g_states[(size_t)2 * NC * NH * HD * NST];
__device__ float g_fd[L * NH];

__device__ __align__(16) __half g_uh[(size_t)L * DM];
__device__ __align__(16) __half g_wi[(size_t)DPROJ * DM];
__device__ __align__(16) __half g_ynh[(size_t)L * DIN];
__device__ __align__(16) __half g_wo[(size_t)DM * DIN];

__device__ __forceinline__ float sigmoidf_(float x) { return 1.f / (1.f + __expf(-x)); }

__device__ __forceinline__ uint32_t smem_u32(const void* p) {
    uint32_t a;
    asm("{ .reg .u64 tmp; cvta.to.shared.u64 tmp, %1; cvt.u32.u64 %0, tmp; }" : "=r"(a) : "l"(p));
    return a;
}
__device__ __forceinline__ void cp_async16(uint32_t dst, const void* src, int srcsize) {
    asm volatile("cp.async.cg.shared.global [%0], [%1], 16, %2;"
                 :: "r"(dst), "l"(src), "r"(srcsize));
}
#define CP_COMMIT() asm volatile("cp.async.commit_group;" ::: "memory")
#define CP_WAIT1()  asm volatile("cp.async.wait_group 1;"  ::: "memory")
#define CP_WAIT0()  asm volatile("cp.async.wait_group 0;"  ::: "memory")

__device__ __forceinline__ void ldsm4(uint32_t* r, uint32_t addr) {
    asm volatile("ldmatrix.sync.aligned.m8n8.x4.shared.b16 {%0,%1,%2,%3}, [%4];"
                 : "=r"(r[0]), "=r"(r[1]), "=r"(r[2]), "=r"(r[3]) : "r"(addr));
}
__device__ __forceinline__ void mma16816h(float* c, const uint32_t* a, uint32_t b0, uint32_t b1) {
    asm volatile("mma.sync.aligned.m16n8k16.row.col.f32.f16.f16.f32 "
                 "{%0,%1,%2,%3}, {%4,%5,%6,%7}, {%8,%9}, {%0,%1,%2,%3};"
                 : "+f"(c[0]), "+f"(c[1]), "+f"(c[2]), "+f"(c[3])
                 : "r"(a[0]), "r"(a[1]), "r"(a[2]), "r"(a[3]), "r"(b0), "r"(b1));
}

// ---- packed f32x2 FMA (Blackwell FFMA2; only reachable via PTX) ----
__device__ __forceinline__ void fma2(unsigned long long& acc,
                                     unsigned long long a, unsigned long long b) {
    asm("fma.rn.f32x2 %0, %1, %2, %0;" : "+l"(acc) : "l"(a), "l"(b));
}
__device__ __forceinline__ unsigned long long pk2(float a, float b) {
    unsigned long long r;
    asm("mov.b64 %0, {%1, %2};" : "=l"(r) : "f"(a), "f"(b));
    return r;
}
__device__ __forceinline__ void upk2(unsigned long long v, float& a, float& b) {
    asm("mov.b64 {%0, %1}, %2;" : "=f"(a), "=f"(b) : "l"(v));
}

// ---------------- fp32 -> fp16 ----------------
__global__ void cvt_h_kernel(const float* __restrict__ x, __half* __restrict__ o, size_t n4) {
    size_t i = (size_t)blockIdx.x * blockDim.x + threadIdx.x;
    if (i >= n4) return;
    float4 v = ((const float4*)x)[i];
    __half2 a = __floats2half2_rn(v.x, v.y);
    __half2 b = __floats2half2_rn(v.z, v.w);
    ((uint2*)o)[i] = make_uint2(*(uint32_t*)&a, *(uint32_t*)&b);
}

// ===== mma.sync fp16 1-term GEMM, 2-stage cp.async pipeline =====
#define KC 32
#define APAD 40

__global__ __launch_bounds__(256, 2) void gemm_1t(
    const __half* __restrict__ Ah, const __half* __restrict__ Bw,
    float* __restrict__ Cc, int Ntot, int Ktot) {
    extern __shared__ __align__(16) __half sm[];
    const int tid = threadIdx.x;
    const int bRow = blockIdx.y * 128, bCol = blockIdx.x * 128;
    const int wid = tid >> 5, lane = tid & 31;
    const int wm = (wid >> 2) * 64, wn = (wid & 3) * 32;

    __half* sp[2][2];
#pragma unroll
    for (int s = 0; s < 2; s++)
#pragma unroll
        for (int o = 0; o < 2; o++) sp[s][o] = sm + ((s * 2 + o) * 128 * APAD);

    float acc[4][4][4];
#pragma unroll
    for (int i = 0; i < 4; i++)
#pragma unroll
        for (int j = 0; j < 4; j++)
#pragma unroll
            for (int q = 0; q < 4; q++) acc[i][j][q] = 0.f;

    const int nst = Ktot / KC;

    auto issue = [&](int s, int c) {
        int kt = c * KC;
#pragma unroll
        for (int i = 0; i < 2; i++) {
            int u = tid + i * 256;
            int r = u >> 2, kc = (u & 3) * 8;
            size_t ga = (size_t)(bRow + r) * Ktot + kt + kc;
            cp_async16(smem_u32(sp[s][0] + r * APAD + kc), Ah + ga, 16);
            int ok = (bCol + r) < Ntot ? 16 : 0;
            size_t gb = ok ? ((size_t)(bCol + r) * Ktot + kt + kc) : 0;
            cp_async16(smem_u32(sp[s][1] + r * APAD + kc), Bw + gb, ok);
        }
    };

    issue(0, 0);
    CP_COMMIT();

    const int ar = lane & 15, ac = (lane >> 4) * 8;
    for (int c = 0; c < nst; c++) {
        if (c + 1 < nst) { issue((c + 1) & 1, c + 1); CP_COMMIT(); CP_WAIT1(); }
        else CP_WAIT0();
        __syncthreads();
        const __half* sa = sp[c & 1][0];
        const __half* sb = sp[c & 1][1];
#pragma unroll
        for (int kk = 0; kk < 2; kk++) {
            int k0 = kk * 16;
            uint32_t bf[2][4];
#pragma unroll
            for (int bt = 0; bt < 2; bt++)
                ldsm4(bf[bt], smem_u32(sb + (wn + bt * 16 + ar) * APAD + k0 + ac));
#pragma unroll
            for (int mt = 0; mt < 4; mt++) {
                uint32_t af[4];
                ldsm4(af, smem_u32(sa + (wm + mt * 16 + ar) * APAD + k0 + ac));
#pragma unroll
                for (int nt = 0; nt < 4; nt++) {
                    int bt = nt >> 1, sel = nt & 1;
                    mma16816h(acc[mt][nt], af, bf[bt][sel], bf[bt][sel + 2]);
                }
            }
        }
        __syncthreads();
    }

    const int g = lane >> 2, t4 = lane & 3;
#pragma unroll
    for (int mt = 0; mt < 4; mt++) {
#pragma unroll
        for (int nt = 0; nt < 4; nt++) {
            int row = bRow + wm + mt * 16 + g;
            int col = bCol + wn + nt * 8 + t4 * 2;
            if (col < Ntot) {
                float* p0 = Cc + (size_t)row * Ntot + col;
                p0[0] = acc[mt][nt][0];
                p0[1] = acc[mt][nt][1];
                float* p1 = p0 + (size_t)8 * Ntot;
                p1[0] = acc[mt][nt][2];
                p1[1] = acc[mt][nt][3];
            }
        }
    }
}

// ---------------- 64x64-tile batched NT SGEMM for G = C B^T ----------------
__global__ __launch_bounds__(256) void sgemm64_nt(const float* __restrict__ A,
                                                  const float* __restrict__ B,
                                                  float* __restrict__ C) {
    A += (size_t)blockIdx.z * CHK * NST;
    B += (size_t)blockIdx.z * CHK * NST;
    C += (size_t)blockIdx.z * CHK * CHK;
    __shared__ float As[16][68];
    __shared__ float Bs[16][68];
    int tid = threadIdx.x;
    int bRow = blockIdx.y * 64, bCol = blockIdx.x * 64;
    int tx = tid & 15, ty = tid >> 4;
    float acc[4][4] = {};
    int lr = tid >> 2, lk = (tid & 3) * 4;
    for (int kt = 0; kt < NST; kt += 16) {
        {
            float4 v = *(const float4*)(A + (size_t)(bRow + lr) * NST + kt + lk);
            As[lk][lr] = v.x; As[lk + 1][lr] = v.y; As[lk + 2][lr] = v.z; As[lk + 3][lr] = v.w;
            float4 w = *(const float4*)(B + (size_t)(bCol + lr) * NST + kt + lk);
            Bs[lk][lr] = w.x; Bs[lk + 1][lr] = w.y; Bs[lk + 2][lr] = w.z; Bs[lk + 3][lr] = w.w;
        }
        __syncthreads();
#pragma unroll
        for (int k = 0; k < 16; k++) {
            float4 ra = *(const float4*)&As[k][ty * 4];
            float4 rb = *(const float4*)&Bs[k][tx * 4];
            float a0 = ra.x, a1 = ra.y, a2 = ra.z, a3 = ra.w;
            acc[0][0] += a0 * rb.x; acc[0][1] += a0 * rb.y; acc[0][2] += a0 * rb.z; acc[0][3] += a0 * rb.w;
            acc[1][0] += a1 * rb.x; acc[1][1] += a1 * rb.y; acc[1][2] += a1 * rb.z; acc[1][3] += a1 * rb.w;
            acc[2][0] += a2 * rb.x; acc[2][1] += a2 * rb.y; acc[2][2] += a2 * rb.z; acc[2][3] += a2 * rb.w;
            acc[3][0] += a3 * rb.x; acc[3][1] += a3 * rb.y; acc[3][2] += a3 * rb.z; acc[3][3] += a3 * rb.w;
        }
        __syncthreads();
    }
#pragma unroll
    for (int i = 0; i < 4; i++) {
        float* p = C + (size_t)(bRow + ty * 4 + i) * CHK + bCol + tx * 4;
        p[0] = acc[i][0]; p[1] = acc[i][1]; p[2] = acc[i][2]; p[3] = acc[i][3];
    }
}

// ---------------- depthwise causal conv (k=4) + bias + silu, float4 over channels ----------------
__global__ void conv_kernel(const float* __restrict__ cw, const float* __restrict__ cb) {
    size_t idx = (size_t)blockIdx.x * blockDim.x + threadIdx.x;
    if (idx >= (size_t)L * (CONVD / 4)) return;
    int c4 = (int)(idx % (CONVD / 4)) * 4;
    int t = (int)(idx / (CONVD / 4));
    float4 b = *(const float4*)(cb + c4);
    float4 acc = b;
    float4 w0 = *(const float4*)(cw + (c4 + 0) * 4);
    float4 w1 = *(const float4*)(cw + (c4 + 1) * 4);
    float4 w2 = *(const float4*)(cw + (c4 + 2) * 4);
    float4 w3 = *(const float4*)(cw + (c4 + 3) * 4);
    const float* wk0 = (const float*)&w0;
    const float* wk1 = (const float*)&w1;
    const float* wk2 = (const float*)&w2;
    const float* wk3 = (const float*)&w3;
#pragma unroll
    for (int k = 0; k < 4; k++) {
        int ts = t - 3 + k;
        if (ts >= 0) {
            float4 v = *(const float4*)(g_zx + (size_t)ts * DPROJ + DIN + c4);
            acc.x += wk0[k] * v.x;
            acc.y += wk1[k] * v.y;
            acc.z += wk2[k] * v.z;
            acc.w += wk3[k] * v.w;
        }
    }
    acc.x *= sigmoidf_(acc.x);
    acc.y *= sigmoidf_(acc.y);
    acc.z *= sigmoidf_(acc.z);
    acc.w *= sigmoidf_(acc.w);
    *(float4*)(g_xc + (size_t)t * CONVD + c4) = acc;
}

// ---------------- dt (with direction flip) + softplus ----------------
__global__ void dt_kernel(const float* __restrict__ dt_bias) {
    int idx = blockIdx.x * blockDim.x + threadIdx.x;
    if (idx >= 2 * L * NH) return;
    int h = idx & 31;
    int t = (idx >> 5) & (L - 1);
    int dir = idx >> 17;
    int ts = dir ? (L - 1 - t) : t;
    float v = g_zx[(size_t)ts * DPROJ + DIN + CONVD + dir * NH + h] + dt_bias[h];
    g_dt2[idx] = (v > 20.f) ? v : log1pf(expf(v));
}

// ---------------- B/C split per direction (flip for dir1) ----------------
__global__ void prep_bc_kernel() {
    int idx = blockIdx.x * blockDim.x + threadIdx.x;
    if (idx >= 2 * L * NST) return;
    int n = idx & 127;
    int t = (idx >> 7) & (L - 1);
    int dir = idx >> 19;
    int ts = dir ? (L - 1 - t) : t;
    int off = dir ? 256 : 0;
    const float* p = g_xc + (size_t)ts * CONVD + DIN + off;
    g_Bm[idx] = p[n];
    g_Cm[idx] = p[NST + n];
}

// ---------------- per-chunk cumsum of A*dt ----------------
__global__ void acs_kernel(const float* __restrict__ A_log) {
    int c = blockIdx.x, dir = blockIdx.y, h = threadIdx.x;
    float Ah = -expf(A_log[h]);
    float cum = 0.f;
    float* out = g_Acs + (((dir * NC + c) * NH + h) << 7);
    const float* dtp = g_dt2 + ((size_t)(dir * L + c * CHK)) * NH + h;
    for (int l = 0; l < CHK; l++) {
        cum += Ah * dtp[l * NH];
        out[l] = cum;
    }
}

// ---------------- per (dir,chunk,head): Y_diag = (G.*Lmat)@xdt ; states = B^T @ (decay.*xdt) ----
__global__ __launch_bounds__(256) void ydiag_states_kernel() {
    int b = blockIdx.x;
    int h = b & 31, c = (b >> 5) & 31, dir = b >> 10;
    int tid = threadIdx.x;
    __shared__ float sAcs[CHK];
    __shared__ float sDt[CHK];
    __shared__ float sCv[CHK];
    __shared__ float sR[CHK][8];
    __shared__ __align__(16) float sMlT[16][132];
    __shared__ __align__(16) float sXs[16][68];
    __shared__ __align__(16) float sB[16][132];
    __shared__ __align__(16) float sXd[16][68];
    if (tid < CHK) {
        sAcs[tid] = g_Acs[(b << 7) + tid];
        sDt[tid] = g_dt2[((size_t)(dir * L + c * CHK + tid)) * NH + h];
    }
    __syncthreads();
    if (tid < CHK) sCv[tid] = __expf(sAcs[tid | 15] - sAcs[tid]);
    {
        int i0 = tid * 4;
#pragma unroll
        for (int q = 0; q < 4; q++) {
            int idx = i0 + q;
            int l = idx >> 3, st = idx & 7;
            sR[l][st] = __expf(fminf(sAcs[l] - sAcs[st * 16 + 15], 85.f));
        }
    }
    __syncthreads();
    const float* Gp = g_G + ((size_t)(dir * NC + c) << 14);
    int tx = tid & 15, ty = tid >> 4;
    unsigned long long accp[8][2] = {};
    int l0 = tid >> 1, skb = (tid & 1) * 8;
    for (int st = 0; st < 8; st++) {
        {
            float r = sR[l0][st];
#pragma unroll
            for (int i = 0; i < 8; i++) {
                int s = st * 16 + skb + i;
                float g = Gp[l0 * CHK + s];
                sMlT[skb + i][l0] = (l0 >= s) ? g * r * sCv[s] : 0.f;
            }
        }
        {
            int sk = tid >> 4, p0 = (tid & 15) * 4;
            int l = st * 16 + sk;
            int tg = c * CHK + l;
            int ts = dir ? (L - 1 - tg) : tg;
            float dtv = sDt[l];
            float4 v = *(const float4*)(g_xc + (size_t)ts * CONVD + h * HD + p0);
            sXs[sk][p0] = v.x * dtv; sXs[sk][p0 + 1] = v.y * dtv;
            sXs[sk][p0 + 2] = v.z * dtv; sXs[sk][p0 + 3] = v.w * dtv;
        }
        __syncthreads();
#pragma unroll
        for (int sk = 0; sk < 16; sk++) {
            unsigned long long xp0 = *(const unsigned long long*)&sXs[sk][tx * 4];
            unsigned long long xp1 = *(const unsigned long long*)&sXs[sk][tx * 4 + 2];
            float4 m0 = *(const float4*)&sMlT[sk][ty * 8];
            float4 m1 = *(const float4*)&sMlT[sk][ty * 8 + 4];
            float mm[8] = {m0.x, m0.y, m0.z, m0.w, m1.x, m1.y, m1.z, m1.w};
#pragma unroll
            for (int i = 0; i < 8; i++) {
                unsigned long long mp = pk2(mm[i], mm[i]);
                fma2(accp[i][0], mp, xp0);
                fma2(accp[i][1], mp, xp1);
            }
        }
        __syncthreads();
    }
    float* Yp = g_Yd + ((size_t)(dir * L + c * CHK)) * DIN + h * HD;
#pragma unroll
    for (int i = 0; i < 8; i++) {
        float a0, a1, a2, a3;
        upk2(accp[i][0], a0, a1);
        upk2(accp[i][1], a2, a3);
        float* p = Yp + (size_t)(ty * 8 + i) * DIN + tx * 4;
        p[0] = a0; p[1] = a1; p[2] = a2; p[3] = a3;
    }

    // ---- states ----
    unsigned long long accSp[8][2] = {};
    int n0 = (tid & 31) * 4;
    int p0s = (tid >> 5) * 8;
    float lastA = sAcs[127];
    const float* Bp = g_Bm + ((size_t)(dir * L + c * CHK)) * NST;
    for (int lt = 0; lt < 8; lt++) {
        {
            int lk = tid >> 4, nb = (tid & 15) * 8;
            float4 v0 = *(const float4*)(Bp + (size_t)(lt * 16 + lk) * NST + nb);
            float4 v1 = *(const float4*)(Bp + (size_t)(lt * 16 + lk) * NST + nb + 4);
            sB[lk][nb] = v0.x; sB[lk][nb + 1] = v0.y; sB[lk][nb + 2] = v0.z; sB[lk][nb + 3] = v0.w;
            sB[lk][nb + 4] = v1.x; sB[lk][nb + 5] = v1.y; sB[lk][nb + 6] = v1.z; sB[lk][nb + 7] = v1.w;
            int pb = (tid & 15) * 4;
            int l = lt * 16 + lk;
            int tg = c * CHK + l;
            int ts = dir ? (L - 1 - tg) : tg;
            float dec = __expf(lastA - sAcs[l]) * sDt[l];
            float4 xv = *(const float4*)(g_xc + (size_t)ts * CONVD + h * HD + pb);
            sXd[lk][pb] = xv.x * dec; sXd[lk][pb + 1] = xv.y * dec;
            sXd[lk][pb + 2] = xv.z * dec; sXd[lk][pb + 3] = xv.w * dec;
        }
        __syncthreads();
#pragma unroll
        for (int lk2 = 0; lk2 < 16; lk2++) {
            float4 p0v = *(const float4*)&sXd[lk2][p0s];
            float4 p1v = *(const float4*)&sXd[lk2][p0s + 4];
            float pv[8] = {p0v.x, p0v.y, p0v.z, p0v.w, p1v.x, p1v.y, p1v.z, p1v.w};
            unsigned long long np0 = *(const unsigned long long*)&sB[lk2][n0];
            unsigned long long np1 = *(const unsigned long long*)&sB[lk2][n0 + 2];
#pragma unroll
            for (int i = 0; i < 8; i++) {
                unsigned long long pp = pk2(pv[i], pv[i]);
                fma2(accSp[i][0], pp, np0);
                fma2(accSp[i][1], pp, np1);
            }
        }
        __syncthreads();
    }
    float* Sp = g_states + ((size_t)b << 13);
#pragma unroll
    for (int i = 0; i < 8; i++) {
        float a0, a1, a2, a3;
        upk2(accSp[i][0], a0, a1);
        upk2(accSp[i][1], a2, a3);
        float* p = Sp + (size_t)(p0s + i) * NST + n0;
        p[0] = a0; p[1] = a1; p[2] = a2; p[3] = a3;
    }
}

// ---------------- inter-chunk recurrence (8-way split per (dir,h)) ----------------
__global__ void recur_kernel() {
    int bi = blockIdx.x;
    int seg = bi & 7, hh = bi >> 3;
    int dir = hh >> 5, h = hh & 31;
    int tid = threadIdx.x;
    float Hreg[4] = {0.f, 0.f, 0.f, 0.f};
    for (int c = 0; c < NC; c++) {
        int sb = (dir * NC + c) * NH + h;
        float dec = __expf(g_Acs[(sb << 7) + 127]);
        size_t base = ((size_t)sb << 13) + seg * 1024;
#pragma unroll
        for (int k = 0; k < 4; k++) {
            size_t off = base + tid + k * 256;
            float s = g_states[off];
            g_states[off] = Hreg[k];
            Hreg[k] = dec * Hreg[k] + s;
        }
    }
}

// ---------------- Y_off = exp(Acs[l]) * C @ state^T ; Yd += Y_off + x*D ----------------
__global__ __launch_bounds__(256) void yoff_kernel(const float* __restrict__ Dv) {
    int b = blockIdx.x;
    int h = b & 31, c = (b >> 5) & 31, dir = b >> 10;
    int tid = threadIdx.x;
    __shared__ float sAcs[CHK];
    __shared__ __align__(16) float sCT[16][132];
    __shared__ __align__(16) float sST[16][68];
    if (tid < CHK) sAcs[tid] = g_Acs[(b << 7) + tid];
    __syncthreads();
    const float* Cp = g_Cm + ((size_t)(dir * L + c * CHK)) * NST;
    const float* Sp = g_states + ((size_t)b << 13);
    int tx = tid & 15, ty = tid >> 4;
    unsigned long long accp[8][2] = {};
    int l0 = tid >> 1, nkb = (tid & 1) * 8;
    int p1 = tid >> 2, nkb2 = (tid & 3) * 4;
    for (int nt = 0; nt < 8; nt++) {
#pragma unroll
        for (int i = 0; i < 8; i++)
            sCT[nkb + i][l0] = Cp[(size_t)l0 * NST + nt * 16 + nkb + i];
        {
            float4 v = *(const float4*)(Sp + (size_t)p1 * NST + nt * 16 + nkb2);
            sST[nkb2][p1] = v.x; sST[nkb2 + 1][p1] = v.y;
            sST[nkb2 + 2][p1] = v.z; sST[nkb2 + 3][p1] = v.w;
        }
        __syncthreads();
#pragma unroll
        for (int nk = 0; nk < 16; nk++) {
            unsigned long long sp0 = *(const unsigned long long*)&sST[nk][tx * 4];
            unsigned long long sp1 = *(const unsigned long long*)&sST[nk][tx * 4 + 2];
            float4 c0 = *(const float4*)&sCT[nk][ty * 8];
            float4 c1 = *(const float4*)&sCT[nk][ty * 8 + 4];
            float cv[8] = {c0.x, c0.y, c0.z, c0.w, c1.x, c1.y, c1.z, c1.w};
#pragma unroll
            for (int i = 0; i < 8; i++) {
                unsigned long long cp = pk2(cv[i], cv[i]);
                fma2(accp[i][0], cp, sp0);
                fma2(accp[i][1], cp, sp1);
            }
        }
        __syncthreads();
    }
    float Dh = Dv[h];
    float* Yp = g_Yd + ((size_t)(dir * L + c * CHK)) * DIN + h * HD;
#pragma unroll
    for (int i = 0; i < 8; i++) {
        int l = ty * 8 + i;
        float e = __expf(sAcs[l]);
        int tglob = c * CHK + l;
        int ts = dir ? (L - 1 - tglob) : tglob;
        const float* xrow = g_xc + (size_t)ts * CONVD + h * HD;
        float a0, a1, a2, a3;
        upk2(accp[i][0], a0, a1);
        upk2(accp[i][1], a2, a3);
        float av[4] = {a0, a1, a2, a3};
#pragma unroll
        for (int j = 0; j < 4; j++) {
            int p = tx * 4 + j;
            size_t o = (size_t)l * DIN + p;
            Yp[o] = Yp[o] + e * av[j] + xrow[p] * Dh;
        }
    }
}

// ---------------- fd = x_og @ fc_D_w^T + D, tiled (32 t-rows per block) ----------------
__global__ __launch_bounds__(256) void fcD_kernel(const float* __restrict__ W,
                                                  const float* __restrict__ Dv) {
    int t0 = blockIdx.x * 32;
    __shared__ float sx[32][132];
    __shared__ float sW[32][132];
    int tid = threadIdx.x;
    int tx = tid & 15, ty = tid >> 4;
    float acc[2][2] = {};
    for (int kc = 0; kc < DIN; kc += 128) {
#pragma unroll
        for (int i = 0; i < 4; i++) {
            int u = tid + i * 256;
            int r = u >> 5, k4 = (u & 31) * 4;
            *(float4*)&sx[r][k4] = *(const float4*)(g_xc + (size_t)(t0 + r) * CONVD + kc + k4);
            *(float4*)&sW[r][k4] = *(const float4*)(W + (size_t)r * DIN + kc + k4);
        }
        __syncthreads();
#pragma unroll 8
        for (int k4 = 0; k4 < 128; k4 += 4) {
            float4 x0 = *(float4*)&sx[ty * 2][k4];
            float4 x1 = *(float4*)&sx[ty * 2 + 1][k4];
            float4 w0 = *(float4*)&sW[tx * 2][k4];
            float4 w1 = *(float4*)&sW[tx * 2 + 1][k4];
            acc[0][0] += x0.x * w0.x + x0.y * w0.y + x0.z * w0.z + x0.w * w0.w;
            acc[0][1] += x0.x * w1.x + x0.y * w1.y + x0.z * w1.z + x0.w * w1.w;
            acc[1][0] += x1.x * w0.x + x1.y * w0.y + x1.z * w0.z + x1.w * w0.w;
            acc[1][1] += x1.x * w1.x + x1.y * w1.y + x1.z * w1.z + x1.w * w1.w;
        }
        __syncthreads();
    }
#pragma unroll
    for (int i = 0; i < 2; i++)
#pragma unroll
        for (int j = 0; j < 2; j++)
            g_fd[(t0 + ty * 2 + i) * NH + tx * 2 + j] = acc[i][j] + Dv[tx * 2 + j];
}

// ---------------- shift + merge dirs + skip + gate + RMSNorm -> fp16 (vectorized) ----------------
__global__ void combine_kernel(const float* __restrict__ norm_w) {
    int t = blockIdx.x;
    int tid = threadIdx.x;
    __shared__ float red[256];
    __shared__ float sc;
    float yg[8];
    float ss = 0.f;
#pragma unroll
    for (int gq = 0; gq < 2; gq++) {
        int d = tid * 4 + gq * 1024;
        float4 yfw = make_float4(0.f, 0.f, 0.f, 0.f);
        if (t > 0) yfw = *(const float4*)(g_Yd + ((size_t)(t - 1)) * DIN + d);
        float4 ybw = make_float4(0.f, 0.f, 0.f, 0.f);
        if (t < L - 1) ybw = *(const float4*)(g_Yd + ((size_t)(L + (L - 2 - t))) * DIN + d);
        float4 xv = *(const float4*)(g_xc + (size_t)t * CONVD + d);
        float fdv = g_fd[t * NH + (d >> 6)];
        float4 zv = *(const float4*)(g_zx + (size_t)t * DPROJ + d);
        float v0 = (yfw.x + ybw.x + xv.x * fdv) * (zv.x * sigmoidf_(zv.x));
        float v1 = (yfw.y + ybw.y + xv.y * fdv) * (zv.y * sigmoidf_(zv.y));
        float v2 = (yfw.z + ybw.z + xv.z * fdv) * (zv.z * sigmoidf_(zv.z));
        float v3 = (yfw.w + ybw.w + xv.w * fdv) * (zv.w * sigmoidf_(zv.w));
        yg[gq * 4] = v0; yg[gq * 4 + 1] = v1; yg[gq * 4 + 2] = v2; yg[gq * 4 + 3] = v3;
        ss += v0 * v0 + v1 * v1 + v2 * v2 + v3 * v3;
    }
    red[tid] = ss;
    __syncthreads();
    for (int o = 128; o > 0; o >>= 1) {
        if (tid < o) red[tid] += red[tid + o];
        __syncthreads();
    }
    if (tid == 0) sc = rsqrtf(red[0] * (1.f / DIN) + EPSV);
    __syncthreads();
    float s = sc;
#pragma unroll
    for (int gq = 0; gq < 2; gq++) {
        int d = tid * 4 + gq * 1024;
        float4 nw = *(const float4*)(norm_w + d);
        __half2 h0 = __floats2half2_rn(yg[gq * 4] * s * nw.x, yg[gq * 4 + 1] * s * nw.y);
        __half2 h1 = __floats2half2_rn(yg[gq * 4 + 2] * s * nw.z, yg[gq * 4 + 3] * s * nw.w);
        *(uint2*)(g_ynh + (size_t)t * DIN + d) = make_uint2(*(uint32_t*)&h0, *(uint32_t*)&h1);
    }
}

extern "C" void kernel_launch(void* const* d_in, const int* in_sizes, int n_in,
                              void* d_out, int out_size) {
    const float* u          = (const float*)d_in[0];
    const float* in_proj_w  = (const float*)d_in[1];
    const float* conv_w     = (const float*)d_in[2];
    const float* conv_b     = (const float*)d_in[3];
    const float* dt_bias    = (const float*)d_in[4];
    const float* A_log      = (const float*)d_in[5];
    const float* Dv         = (const float*)d_in[6];
    const float* fc_D_w     = (const float*)d_in[7];
    const float* norm_w     = (const float*)d_in[8];
    const float* out_proj_w = (const float*)d_in[9];
    float* out = (float*)d_out;

    float *zx, *Bm, *Cm, *G;
    __half *uh, *wi, *ynh, *wo;
    cudaGetSymbolAddress((void**)&zx, g_zx);
    cudaGetSymbolAddress((void**)&Bm, g_Bm);
    cudaGetSymbolAddress((void**)&Cm, g_Cm);
    cudaGetSymbolAddress((void**)&G, g_G);
    cudaGetSymbolAddress((void**)&uh, g_uh);
    cudaGetSymbolAddress((void**)&wi, g_wi);
    cudaGetSymbolAddress((void**)&ynh, g_ynh);
    cudaGetSymbolAddress((void**)&wo, g_wo);

    const int smemB = 2 * 2 * 128 * APAD * 2;  // 40960 B
    cudaFuncSetAttribute(gemm_1t, cudaFuncAttributeMaxDynamicSharedMemorySize, smemB);

    // 0) convert to fp16 (single precision everywhere; error budget allows it)
    cvt_h_kernel<<<((size_t)L * DM / 4 + 255) / 256, 256>>>(u, uh, (size_t)L * DM / 4);
    cvt_h_kernel<<<((size_t)DPROJ * DM / 4 + 255) / 256, 256>>>(in_proj_w, wi, (size_t)DPROJ * DM / 4);
    cvt_h_kernel<<<((size_t)DM * DIN / 4 + 255) / 256, 256>>>(out_proj_w, wo, (size_t)DM * DIN / 4);

    // 1) in_proj (fp16 1-term)
    gemm_1t<<<dim3((DPROJ + 127) / 128, L / 128), 256, smemB>>>(uh, wi, zx, DPROJ, DM);
    // 2) conv + silu (vectorized)
    conv_kernel<<<((size_t)L * (CONVD / 4) + 255) / 256, 256>>>(conv_w, conv_b);
    // 3) dt softplus
    dt_kernel<<<(2 * L * NH + 255) / 256, 256>>>(dt_bias);
    // 4) B/C prep
    prep_bc_kernel<<<(2 * L * NST + 255) / 256, 256>>>();
    // 5) per-chunk cumsum of A*dt
    acs_kernel<<<dim3(NC, 2), 32>>>(A_log);
    // 6) G = C B^T per (dir,chunk)
    sgemm64_nt<<<dim3(2, 2, 2 * NC), 256>>>(Cm, Bm, G);
    // 7) Y_diag + chunk states (f32x2 packed FMA)
    ydiag_states_kernel<<<2 * NC * NH, 256>>>();
    // 8) inter-chunk recurrence
    recur_kernel<<<512, 256>>>();
    // 9) Y_off + x*D (f32x2 packed FMA)
    yoff_kernel<<<2 * NC * NH, 256>>>(Dv);
    // 10) fd
    fcD_kernel<<<L / 32, 256>>>(fc_D_w, Dv);
    // 11) shift/merge/gate/RMSNorm (vectorized, writes fp16)
    combine_kernel<<<L, 256>>>(norm_w);
    // 12) out_proj (fp16 1-term)
    gemm_1t<<<dim3(DM / 128, L / 128), 256, smemB>>>(ynh, wo, out, DM, DIN);
}

// round 17
// speedup vs baseline: 1.3323x; 1.0055x over previous
#include <cuda_runtime.h>
#include <cuda_bf16.h>
#include <cuda_fp16.h>
#include <math.h>
#include <stdint.h>

#define L 4096
#define DM 1024
#define DIN 2048
#define NH 32
#define HD 64
#define NST 128
#define CONVD 2560
#define DPROJ 4672
#define CHK 128
#define NC 32
#define EPSV 1e-5f

// ---------------- scratch (static device globals; no allocation) ----------------
__device__ float g_zx[(size_t)L * DPROJ];
__device__ float g_xc[(size_t)L * CONVD];
__device__ float g_dt2[2 * L * NH];
__device__ float g_Bm[(size_t)2 * L * NST];
__device__ float g_Cm[(size_t)2 * L * NST];
__device__ float g_Acs[2 * NC * NH * CHK];
__device__ float g_G[(size_t)2 * NC * CHK * CHK];
__device__ float g_Yd[(size_t)2 * L * DIN];
__device__ float g_states[(size_t)2 * NC * NH * HD * NST];
__device__ float g_fd[L * NH];

__device__ __align__(16) __half g_uh[(size_t)L * DM];
__device__ __align__(16) __half g_wi[(size_t)DPROJ * DM];
__device__ __align__(16) __half g_ynh[(size_t)L * DIN];
__device__ __align__(16) __half g_wo[(size_t)DM * DIN];

__device__ __forceinline__ float sigmoidf_(float x) { return 1.f / (1.f + __expf(-x)); }

__device__ __forceinline__ uint32_t smem_u32(const void* p) {
    uint32_t a;
    asm("{ .reg .u64 tmp; cvta.to.shared.u64 tmp, %1; cvt.u32.u64 %0, tmp; }" : "=r"(a) : "l"(p));
    return a;
}
__device__ __forceinline__ void cp_async16(uint32_t dst, const void* src, int srcsize) {
    asm volatile("cp.async.cg.shared.global [%0], [%1], 16, %2;"
                 :: "r"(dst), "l"(src), "r"(srcsize));
}
#define CP_COMMIT() asm volatile("cp.async.commit_group;" ::: "memory")
#define CP_WAIT1()  asm volatile("cp.async.wait_group 1;"  ::: "memory")
#define CP_WAIT0()  asm volatile("cp.async.wait_group 0;"  ::: "memory")

__device__ __forceinline__ void ldsm4(uint32_t* r, uint32_t addr) {
    asm volatile("ldmatrix.sync.aligned.m8n8.x4.shared.b16 {%0,%1,%2,%3}, [%4];"
                 : "=r"(r[0]), "=r"(r[1]), "=r"(r[2]), "=r"(r[3]) : "r"(addr));
}
__device__ __forceinline__ void mma16816h(float* c, const uint32_t* a, uint32_t b0, uint32_t b1) {
    asm volatile("mma.sync.aligned.m16n8k16.row.col.f32.f16.f16.f32 "
                 "{%0,%1,%2,%3}, {%4,%5,%6,%7}, {%8,%9}, {%0,%1,%2,%3};"
                 : "+f"(c[0]), "+f"(c[1]), "+f"(c[2]), "+f"(c[3])
                 : "r"(a[0]), "r"(a[1]), "r"(a[2]), "r"(a[3]), "r"(b0), "r"(b1));
}

// ---- packed f32x2 ops (Blackwell FFMA2; only reachable via PTX) ----
__device__ __forceinline__ void fma2(unsigned long long& acc,
                                     unsigned long long a, unsigned long long b) {
    asm("fma.rn.f32x2 %0, %1, %2, %0;" : "+l"(acc) : "l"(a), "l"(b));
}
__device__ __forceinline__ unsigned long long mul2(unsigned long long a, unsigned long long b) {
    unsigned long long r;
    asm("mul.rn.f32x2 %0, %1, %2;" : "=l"(r) : "l"(a), "l"(b));
    return r;
}
__device__ __forceinline__ unsigned long long pk2(float a, float b) {
    unsigned long long r;
    asm("mov.b64 %0, {%1, %2};" : "=l"(r) : "f"(a), "f"(b));
    return r;
}
__device__ __forceinline__ void upk2(unsigned long long v, float& a, float& b) {
    asm("mov.b64 {%0, %1}, %2;" : "=f"(a), "=f"(b) : "l"(v));
}

// ---------------- fp32 -> fp16 ----------------
__global__ void cvt_h_kernel(const float* __restrict__ x, __half* __restrict__ o, size_t n4) {
    size_t i = (size_t)blockIdx.x * blockDim.x + threadIdx.x;
    if (i >= n4) return;
    float4 v = ((const float4*)x)[i];
    __half2 a = __floats2half2_rn(v.x, v.y);
    __half2 b = __floats2half2_rn(v.z, v.w);
    ((uint2*)o)[i] = make_uint2(*(uint32_t*)&a, *(uint32_t*)&b);
}

// ===== mma.sync fp16 1-term GEMM, K-chunk 64, 2-stage cp.async pipeline =====
#define KC 64
#define APAD 72

__global__ __launch_bounds__(256, 2) void gemm_1t(
    const __half* __restrict__ Ah, const __half* __restrict__ Bw,
    float* __restrict__ Cc, int Ntot, int Ktot) {
    extern __shared__ __align__(16) __half sm[];
    const int tid = threadIdx.x;
    const int bRow = blockIdx.y * 128, bCol = blockIdx.x * 128;
    const int wid = tid >> 5, lane = tid & 31;
    const int wm = (wid >> 2) * 64, wn = (wid & 3) * 32;

    __half* sp[2][2];
#pragma unroll
    for (int s = 0; s < 2; s++)
#pragma unroll
        for (int o = 0; o < 2; o++) sp[s][o] = sm + ((s * 2 + o) * 128 * APAD);

    float acc[4][4][4];
#pragma unroll
    for (int i = 0; i < 4; i++)
#pragma unroll
        for (int j = 0; j < 4; j++)
#pragma unroll
            for (int q = 0; q < 4; q++) acc[i][j][q] = 0.f;

    const int nst = Ktot / KC;

    auto issue = [&](int s, int c) {
        int kt = c * KC;
#pragma unroll
        for (int i = 0; i < 4; i++) {
            int u = tid + i * 256;           // 0..1023 8-half units
            int r = u >> 3, kc = (u & 7) * 8;
            size_t ga = (size_t)(bRow + r) * Ktot + kt + kc;
            cp_async16(smem_u32(sp[s][0] + r * APAD + kc), Ah + ga, 16);
            int ok = (bCol + r) < Ntot ? 16 : 0;
            size_t gb = ok ? ((size_t)(bCol + r) * Ktot + kt + kc) : 0;
            cp_async16(smem_u32(sp[s][1] + r * APAD + kc), Bw + gb, ok);
        }
    };

    issue(0, 0);
    CP_COMMIT();

    const int ar = lane & 15, ac = (lane >> 4) * 8;
    for (int c = 0; c < nst; c++) {
        if (c + 1 < nst) { issue((c + 1) & 1, c + 1); CP_COMMIT(); CP_WAIT1(); }
        else CP_WAIT0();
        __syncthreads();
        const __half* sa = sp[c & 1][0];
        const __half* sb = sp[c & 1][1];
#pragma unroll
        for (int kk = 0; kk < 4; kk++) {
            int k0 = kk * 16;
            uint32_t bf[2][4];
#pragma unroll
            for (int bt = 0; bt < 2; bt++)
                ldsm4(bf[bt], smem_u32(sb + (wn + bt * 16 + ar) * APAD + k0 + ac));
#pragma unroll
            for (int mt = 0; mt < 4; mt++) {
                uint32_t af[4];
                ldsm4(af, smem_u32(sa + (wm + mt * 16 + ar) * APAD + k0 + ac));
#pragma unroll
                for (int nt = 0; nt < 4; nt++) {
                    int bt = nt >> 1, sel = nt & 1;
                    mma16816h(acc[mt][nt], af, bf[bt][sel], bf[bt][sel + 2]);
                }
            }
        }
        __syncthreads();
    }

    const int g = lane >> 2, t4 = lane & 3;
#pragma unroll
    for (int mt = 0; mt < 4; mt++) {
#pragma unroll
        for (int nt = 0; nt < 4; nt++) {
            int row = bRow + wm + mt * 16 + g;
            int col = bCol + wn + nt * 8 + t4 * 2;
            if (col < Ntot) {
                float* p0 = Cc + (size_t)row * Ntot + col;
                p0[0] = acc[mt][nt][0];
                p0[1] = acc[mt][nt][1];
                float* p1 = p0 + (size_t)8 * Ntot;
                p1[0] = acc[mt][nt][2];
                p1[1] = acc[mt][nt][3];
            }
        }
    }
}

// ---------------- 64x64-tile batched NT SGEMM for G = C B^T ----------------
__global__ __launch_bounds__(256) void sgemm64_nt(const float* __restrict__ A,
                                                  const float* __restrict__ B,
                                                  float* __restrict__ C) {
    A += (size_t)blockIdx.z * CHK * NST;
    B += (size_t)blockIdx.z * CHK * NST;
    C += (size_t)blockIdx.z * CHK * CHK;
    __shared__ float As[16][68];
    __shared__ float Bs[16][68];
    int tid = threadIdx.x;
    int bRow = blockIdx.y * 64, bCol = blockIdx.x * 64;
    int tx = tid & 15, ty = tid >> 4;
    float acc[4][4] = {};
    int lr = tid >> 2, lk = (tid & 3) * 4;
    for (int kt = 0; kt < NST; kt += 16) {
        {
            float4 v = *(const float4*)(A + (size_t)(bRow + lr) * NST + kt + lk);
            As[lk][lr] = v.x; As[lk + 1][lr] = v.y; As[lk + 2][lr] = v.z; As[lk + 3][lr] = v.w;
            float4 w = *(const float4*)(B + (size_t)(bCol + lr) * NST + kt + lk);
            Bs[lk][lr] = w.x; Bs[lk + 1][lr] = w.y; Bs[lk + 2][lr] = w.z; Bs[lk + 3][lr] = w.w;
        }
        __syncthreads();
#pragma unroll
        for (int k = 0; k < 16; k++) {
            float4 ra = *(const float4*)&As[k][ty * 4];
            float4 rb = *(const float4*)&Bs[k][tx * 4];
            float a0 = ra.x, a1 = ra.y, a2 = ra.z, a3 = ra.w;
            acc[0][0] += a0 * rb.x; acc[0][1] += a0 * rb.y; acc[0][2] += a0 * rb.z; acc[0][3] += a0 * rb.w;
            acc[1][0] += a1 * rb.x; acc[1][1] += a1 * rb.y; acc[1][2] += a1 * rb.z; acc[1][3] += a1 * rb.w;
            acc[2][0] += a2 * rb.x; acc[2][1] += a2 * rb.y; acc[2][2] += a2 * rb.z; acc[2][3] += a2 * rb.w;
            acc[3][0] += a3 * rb.x; acc[3][1] += a3 * rb.y; acc[3][2] += a3 * rb.z; acc[3][3] += a3 * rb.w;
        }
        __syncthreads();
    }
#pragma unroll
    for (int i = 0; i < 4; i++) {
        float* p = C + (size_t)(bRow + ty * 4 + i) * CHK + bCol + tx * 4;
        p[0] = acc[i][0]; p[1] = acc[i][1]; p[2] = acc[i][2]; p[3] = acc[i][3];
    }
}

// ---------------- depthwise causal conv (k=4) + bias + silu, float4 over channels ----------------
__global__ void conv_kernel(const float* __restrict__ cw, const float* __restrict__ cb) {
    size_t idx = (size_t)blockIdx.x * blockDim.x + threadIdx.x;
    if (idx >= (size_t)L * (CONVD / 4)) return;
    int c4 = (int)(idx % (CONVD / 4)) * 4;
    int t = (int)(idx / (CONVD / 4));
    float4 acc = *(const float4*)(cb + c4);
    float4 w0 = *(const float4*)(cw + (c4 + 0) * 4);
    float4 w1 = *(const float4*)(cw + (c4 + 1) * 4);
    float4 w2 = *(const float4*)(cw + (c4 + 2) * 4);
    float4 w3 = *(const float4*)(cw + (c4 + 3) * 4);
    const float* wk0 = (const float*)&w0;
    const float* wk1 = (const float*)&w1;
    const float* wk2 = (const float*)&w2;
    const float* wk3 = (const float*)&w3;
#pragma unroll
    for (int k = 0; k < 4; k++) {
        int ts = t - 3 + k;
        if (ts >= 0) {
            float4 v = *(const float4*)(g_zx + (size_t)ts * DPROJ + DIN + c4);
            acc.x += wk0[k] * v.x;
            acc.y += wk1[k] * v.y;
            acc.z += wk2[k] * v.z;
            acc.w += wk3[k] * v.w;
        }
    }
    acc.x *= sigmoidf_(acc.x);
    acc.y *= sigmoidf_(acc.y);
    acc.z *= sigmoidf_(acc.z);
    acc.w *= sigmoidf_(acc.w);
    *(float4*)(g_xc + (size_t)t * CONVD + c4) = acc;
}

// ---------------- dt (with direction flip) + softplus ----------------
__global__ void dt_kernel(const float* __restrict__ dt_bias) {
    int idx = blockIdx.x * blockDim.x + threadIdx.x;
    if (idx >= 2 * L * NH) return;
    int h = idx & 31;
    int t = (idx >> 5) & (L - 1);
    int dir = idx >> 17;
    int ts = dir ? (L - 1 - t) : t;
    float v = g_zx[(size_t)ts * DPROJ + DIN + CONVD + dir * NH + h] + dt_bias[h];
    g_dt2[idx] = (v > 20.f) ? v : log1pf(expf(v));
}

// ---------------- B/C split per direction (flip for dir1) ----------------
__global__ void prep_bc_kernel() {
    int idx = blockIdx.x * blockDim.x + threadIdx.x;
    if (idx >= 2 * L * NST) return;
    int n = idx & 127;
    int t = (idx >> 7) & (L - 1);
    int dir = idx >> 19;
    int ts = dir ? (L - 1 - t) : t;
    int off = dir ? 256 : 0;
    const float* p = g_xc + (size_t)ts * CONVD + DIN + off;
    g_Bm[idx] = p[n];
    g_Cm[idx] = p[NST + n];
}

// ---------------- per-chunk cumsum of A*dt ----------------
__global__ void acs_kernel(const float* __restrict__ A_log) {
    int c = blockIdx.x, dir = blockIdx.y, h = threadIdx.x;
    float Ah = -expf(A_log[h]);
    float cum = 0.f;
    float* out = g_Acs + (((dir * NC + c) * NH + h) << 7);
    const float* dtp = g_dt2 + ((size_t)(dir * L + c * CHK)) * NH + h;
    for (int l = 0; l < CHK; l++) {
        cum += Ah * dtp[l * NH];
        out[l] = cum;
    }
}

// ---------------- fused per (dir,chunk,head): Y_diag and states in ONE slab loop ----------------
__global__ __launch_bounds__(256) void ydiag_states_kernel() {
    int b = blockIdx.x;
    int h = b & 31, c = (b >> 5) & 31, dir = b >> 10;
    int tid = threadIdx.x;
    __shared__ float sAcs[CHK];
    __shared__ float sDt[CHK];
    __shared__ float sCv[CHK];
    __shared__ float sDec[CHK];
    __shared__ float sR[CHK][8];
    __shared__ __align__(16) float sMlT[16][132];   // [s_in_slab][l]
    __shared__ __align__(16) float sXs[16][68];     // [k][p]  (x*dt)
    __shared__ __align__(16) float sB[16][132];     // [k][n]
    if (tid < CHK) {
        sAcs[tid] = g_Acs[(b << 7) + tid];
        sDt[tid] = g_dt2[((size_t)(dir * L + c * CHK + tid)) * NH + h];
    }
    __syncthreads();
    if (tid < CHK) {
        sCv[tid] = __expf(sAcs[tid | 15] - sAcs[tid]);
        sDec[tid] = __expf(sAcs[127] - sAcs[tid]);
    }
    {
        int i0 = tid * 4;
#pragma unroll
        for (int q = 0; q < 4; q++) {
            int idx = i0 + q;
            int l = idx >> 3, st = idx & 7;
            sR[l][st] = __expf(fminf(sAcs[l] - sAcs[st * 16 + 15], 85.f));
        }
    }
    __syncthreads();
    const float* Gp = g_G + ((size_t)(dir * NC + c) << 14);
    const float* Bp = g_Bm + ((size_t)(dir * L + c * CHK)) * NST;
    int tx = tid & 15, ty = tid >> 4;
    unsigned long long accp[8][2] = {};
    unsigned long long accSp[8][2] = {};
    int l0 = tid >> 1, skb = (tid & 1) * 8;
    int n0 = (tid & 31) * 4;
    int p0s = (tid >> 5) * 8;
    for (int st = 0; st < 8; st++) {
        // build masked-decay M (transposed), x*dt slab, raw B slab
        {
            float r = sR[l0][st];
#pragma unroll
            for (int i = 0; i < 8; i++) {
                int s = st * 16 + skb + i;
                float g = Gp[l0 * CHK + s];
                sMlT[skb + i][l0] = (l0 >= s) ? g * r * sCv[s] : 0.f;
            }
        }
        {
            int sk = tid >> 4, p0 = (tid & 15) * 4;
            int l = st * 16 + sk;
            int tg = c * CHK + l;
            int ts = dir ? (L - 1 - tg) : tg;
            float dtv = sDt[l];
            float4 v = *(const float4*)(g_xc + (size_t)ts * CONVD + h * HD + p0);
            sXs[sk][p0] = v.x * dtv; sXs[sk][p0 + 1] = v.y * dtv;
            sXs[sk][p0 + 2] = v.z * dtv; sXs[sk][p0 + 3] = v.w * dtv;
        }
        {
            int lk = tid >> 4, nb = (tid & 15) * 8;
            float4 v0 = *(const float4*)(Bp + (size_t)(st * 16 + lk) * NST + nb);
            float4 v1 = *(const float4*)(Bp + (size_t)(st * 16 + lk) * NST + nb + 4);
            sB[lk][nb] = v0.x; sB[lk][nb + 1] = v0.y; sB[lk][nb + 2] = v0.z; sB[lk][nb + 3] = v0.w;
            sB[lk][nb + 4] = v1.x; sB[lk][nb + 5] = v1.y; sB[lk][nb + 6] = v1.z; sB[lk][nb + 7] = v1.w;
        }
        __syncthreads();
        // Y_diag accumulation
#pragma unroll
        for (int sk = 0; sk < 16; sk++) {
            unsigned long long xp0 = *(const unsigned long long*)&sXs[sk][tx * 4];
            unsigned long long xp1 = *(const unsigned long long*)&sXs[sk][tx * 4 + 2];
            float4 m0 = *(const float4*)&sMlT[sk][ty * 8];
            float4 m1 = *(const float4*)&sMlT[sk][ty * 8 + 4];
            float mm[8] = {m0.x, m0.y, m0.z, m0.w, m1.x, m1.y, m1.z, m1.w};
#pragma unroll
            for (int i = 0; i < 8; i++) {
                unsigned long long mp = pk2(mm[i], mm[i]);
                fma2(accp[i][0], mp, xp0);
                fma2(accp[i][1], mp, xp1);
            }
        }
        // states accumulation (dec folded onto B side, scaled once per k)
#pragma unroll
        for (int lk2 = 0; lk2 < 16; lk2++) {
            float dec = sDec[st * 16 + lk2];
            unsigned long long dp = pk2(dec, dec);
            unsigned long long np0 = mul2(*(const unsigned long long*)&sB[lk2][n0], dp);
            unsigned long long np1 = mul2(*(const unsigned long long*)&sB[lk2][n0 + 2], dp);
            float4 p0v = *(const float4*)&sXs[lk2][p0s];
            float4 p1v = *(const float4*)&sXs[lk2][p0s + 4];
            float pv[8] = {p0v.x, p0v.y, p0v.z, p0v.w, p1v.x, p1v.y, p1v.z, p1v.w};
#pragma unroll
            for (int i = 0; i < 8; i++) {
                unsigned long long pp = pk2(pv[i], pv[i]);
                fma2(accSp[i][0], pp, np0);
                fma2(accSp[i][1], pp, np1);
            }
        }
        __syncthreads();
    }
    float* Yp = g_Yd + ((size_t)(dir * L + c * CHK)) * DIN + h * HD;
#pragma unroll
    for (int i = 0; i < 8; i++) {
        float a0, a1, a2, a3;
        upk2(accp[i][0], a0, a1);
        upk2(accp[i][1], a2, a3);
        float* p = Yp + (size_t)(ty * 8 + i) * DIN + tx * 4;
        p[0] = a0; p[1] = a1; p[2] = a2; p[3] = a3;
    }
    float* Sp = g_states + ((size_t)b << 13);
#pragma unroll
    for (int i = 0; i < 8; i++) {
        float a0, a1, a2, a3;
        upk2(accSp[i][0], a0, a1);
        upk2(accSp[i][1], a2, a3);
        float* p = Sp + (size_t)(p0s + i) * NST + n0;
        p[0] = a0; p[1] = a1; p[2] = a2; p[3] = a3;
    }
}

// ---------------- inter-chunk recurrence (8-way split per (dir,h)) ----------------
__global__ void recur_kernel() {
    int bi = blockIdx.x;
    int seg = bi & 7, hh = bi >> 3;
    int dir = hh >> 5, h = hh & 31;
    int tid = threadIdx.x;
    float Hreg[4] = {0.f, 0.f, 0.f, 0.f};
    for (int c = 0; c < NC; c++) {
        int sb = (dir * NC + c) * NH + h;
        float dec = __expf(g_Acs[(sb << 7) + 127]);
        size_t base = ((size_t)sb << 13) + seg * 1024;
#pragma unroll
        for (int k = 0; k < 4; k++) {
            size_t off = base + tid + k * 256;
            float s = g_states[off];
            g_states[off] = Hreg[k];
            Hreg[k] = dec * Hreg[k] + s;
        }
    }
}

// ---------------- Y_off = exp(Acs[l]) * C @ state^T ; Yd += Y_off + x*D ----------------
__global__ __launch_bounds__(256) void yoff_kernel(const float* __restrict__ Dv) {
    int b = blockIdx.x;
    int h = b & 31, c = (b >> 5) & 31, dir = b >> 10;
    int tid = threadIdx.x;
    __shared__ float sAcs[CHK];
    __shared__ __align__(16) float sCT[16][132];
    __shared__ __align__(16) float sST[16][68];
    if (tid < CHK) sAcs[tid] = g_Acs[(b << 7) + tid];
    __syncthreads();
    const float* Cp = g_Cm + ((size_t)(dir * L + c * CHK)) * NST;
    const float* Sp = g_states + ((size_t)b << 13);
    int tx = tid & 15, ty = tid >> 4;
    unsigned long long accp[8][2] = {};
    int l0 = tid >> 1, nkb = (tid & 1) * 8;
    int p1 = tid >> 2, nkb2 = (tid & 3) * 4;
    for (int nt = 0; nt < 8; nt++) {
#pragma unroll
        for (int i = 0; i < 8; i++)
            sCT[nkb + i][l0] = Cp[(size_t)l0 * NST + nt * 16 + nkb + i];
        {
            float4 v = *(const float4*)(Sp + (size_t)p1 * NST + nt * 16 + nkb2);
            sST[nkb2][p1] = v.x; sST[nkb2 + 1][p1] = v.y;
            sST[nkb2 + 2][p1] = v.z; sST[nkb2 + 3][p1] = v.w;
        }
        __syncthreads();
#pragma unroll
        for (int nk = 0; nk < 16; nk++) {
            unsigned long long sp0 = *(const unsigned long long*)&sST[nk][tx * 4];
            unsigned long long sp1 = *(const unsigned long long*)&sST[nk][tx * 4 + 2];
            float4 c0 = *(const float4*)&sCT[nk][ty * 8];
            float4 c1 = *(const float4*)&sCT[nk][ty * 8 + 4];
            float cv[8] = {c0.x, c0.y, c0.z, c0.w, c1.x, c1.y, c1.z, c1.w};
#pragma unroll
            for (int i = 0; i < 8; i++) {
                unsigned long long cp = pk2(cv[i], cv[i]);
                fma2(accp[i][0], cp, sp0);
                fma2(accp[i][1], cp, sp1);
            }
        }
        __syncthreads();
    }
    float Dh = Dv[h];
    float* Yp = g_Yd + ((size_t)(dir * L + c * CHK)) * DIN + h * HD;
#pragma unroll
    for (int i = 0; i < 8; i++) {
        int l = ty * 8 + i;
        float e = __expf(sAcs[l]);
        int tglob = c * CHK + l;
        int ts = dir ? (L - 1 - tglob) : tglob;
        const float* xrow = g_xc + (size_t)ts * CONVD + h * HD;
        float a0, a1, a2, a3;
        upk2(accp[i][0], a0, a1);
        upk2(accp[i][1], a2, a3);
        float av[4] = {a0, a1, a2, a3};
#pragma unroll
        for (int j = 0; j < 4; j++) {
            int p = tx * 4 + j;
            size_t o = (size_t)l * DIN + p;
            Yp[o] = Yp[o] + e * av[j] + xrow[p] * Dh;
        }
    }
}

// ---------------- fd = x_og @ fc_D_w^T + D, tiled (32 t-rows per block) ----------------
__global__ __launch_bounds__(256) void fcD_kernel(const float* __restrict__ W,
                                                  const float* __restrict__ Dv) {
    int t0 = blockIdx.x * 32;
    __shared__ float sx[32][132];
    __shared__ float sW[32][132];
    int tid = threadIdx.x;
    int tx = tid & 15, ty = tid >> 4;
    float acc[2][2] = {};
    for (int kc = 0; kc < DIN; kc += 128) {
#pragma unroll
        for (int i = 0; i < 4; i++) {
            int u = tid + i * 256;
            int r = u >> 5, k4 = (u & 31) * 4;
            *(float4*)&sx[r][k4] = *(const float4*)(g_xc + (size_t)(t0 + r) * CONVD + kc + k4);
            *(float4*)&sW[r][k4] = *(const float4*)(W + (size_t)r * DIN + kc + k4);
        }
        __syncthreads();
#pragma unroll 8
        for (int k4 = 0; k4 < 128; k4 += 4) {
            float4 x0 = *(float4*)&sx[ty * 2][k4];
            float4 x1 = *(float4*)&sx[ty * 2 + 1][k4];
            float4 w0 = *(float4*)&sW[tx * 2][k4];
            float4 w1 = *(float4*)&sW[tx * 2 + 1][k4];
            acc[0][0] += x0.x * w0.x + x0.y * w0.y + x0.z * w0.z + x0.w * w0.w;
            acc[0][1] += x0.x * w1.x + x0.y * w1.y + x0.z * w1.z + x0.w * w1.w;
            acc[1][0] += x1.x * w0.x + x1.y * w0.y + x1.z * w0.z + x1.w * w0.w;
            acc[1][1] += x1.x * w1.x + x1.y * w1.y + x1.z * w1.z + x1.w * w1.w;
        }
        __syncthreads();
    }
#pragma unroll
    for (int i = 0; i < 2; i++)
#pragma unroll
        for (int j = 0; j < 2; j++)
            g_fd[(t0 + ty * 2 + i) * NH + tx * 2 + j] = acc[i][j] + Dv[tx * 2 + j];
}

// ---------------- shift + merge dirs + skip + gate + RMSNorm -> fp16 (vectorized) ----------------
__global__ void combine_kernel(const float* __restrict__ norm_w) {
    int t = blockIdx.x;
    int tid = threadIdx.x;
    __shared__ float red[256];
    __shared__ float sc;
    float yg[8];
    float ss = 0.f;
#pragma unroll
    for (int gq = 0; gq < 2; gq++) {
        int d = tid * 4 + gq * 1024;
        float4 yfw = make_float4(0.f, 0.f, 0.f, 0.f);
        if (t > 0) yfw = *(const float4*)(g_Yd + ((size_t)(t - 1)) * DIN + d);
        float4 ybw = make_float4(0.f, 0.f, 0.f, 0.f);
        if (t < L - 1) ybw = *(const float4*)(g_Yd + ((size_t)(L + (L - 2 - t))) * DIN + d);
        float4 xv = *(const float4*)(g_xc + (size_t)t * CONVD + d);
        float fdv = g_fd[t * NH + (d >> 6)];
        float4 zv = *(const float4*)(g_zx + (size_t)t * DPROJ + d);
        float v0 = (yfw.x + ybw.x + xv.x * fdv) * (zv.x * sigmoidf_(zv.x));
        float v1 = (yfw.y + ybw.y + xv.y * fdv) * (zv.y * sigmoidf_(zv.y));
        float v2 = (yfw.z + ybw.z + xv.z * fdv) * (zv.z * sigmoidf_(zv.z));
        float v3 = (yfw.w + ybw.w + xv.w * fdv) * (zv.w * sigmoidf_(zv.w));
        yg[gq * 4] = v0; yg[gq * 4 + 1] = v1; yg[gq * 4 + 2] = v2; yg[gq * 4 + 3] = v3;
        ss += v0 * v0 + v1 * v1 + v2 * v2 + v3 * v3;
    }
    red[tid] = ss;
    __syncthreads();
    for (int o = 128; o > 0; o >>= 1) {
        if (tid < o) red[tid] += red[tid + o];
        __syncthreads();
    }
    if (tid == 0) sc = rsqrtf(red[0] * (1.f / DIN) + EPSV);
    __syncthreads();
    float s = sc;
#pragma unroll
    for (int gq = 0; gq < 2; gq++) {
        int d = tid * 4 + gq * 1024;
        float4 nw = *(const float4*)(norm_w + d);
        __half2 h0 = __floats2half2_rn(yg[gq * 4] * s * nw.x, yg[gq * 4 + 1] * s * nw.y);
        __half2 h1 = __floats2half2_rn(yg[gq * 4 + 2] * s * nw.z, yg[gq * 4 + 3] * s * nw.w);
        *(uint2*)(g_ynh + (size_t)t * DIN + d) = make_uint2(*(uint32_t*)&h0, *(uint32_t*)&h1);
    }
}

extern "C" void kernel_launch(void* const* d_in, const int* in_sizes, int n_in,
                              void* d_out, int out_size) {
    const float* u          = (const float*)d_in[0];
    const float* in_proj_w  = (const float*)d_in[1];
    const float* conv_w     = (const float*)d_in[2];
    const float* conv_b     = (const float*)d_in[3];
    const float* dt_bias    = (const float*)d_in[4];
    const float* A_log      = (const float*)d_in[5];
    const float* Dv         = (const float*)d_in[6];
    const float* fc_D_w     = (const float*)d_in[7];
    const float* norm_w     = (const float*)d_in[8];
    const float* out_proj_w = (const float*)d_in[9];
    float* out = (float*)d_out;

    float *zx, *Bm, *Cm, *G;
    __half *uh, *wi, *ynh, *wo;
    cudaGetSymbolAddress((void**)&zx, g_zx);
    cudaGetSymbolAddress((void**)&Bm, g_Bm);
    cudaGetSymbolAddress((void**)&Cm, g_Cm);
    cudaGetSymbolAddress((void**)&G, g_G);
    cudaGetSymbolAddress((void**)&uh, g_uh);
    cudaGetSymbolAddress((void**)&wi, g_wi);
    cudaGetSymbolAddress((void**)&ynh, g_ynh);
    cudaGetSymbolAddress((void**)&wo, g_wo);

    const int smemB = 2 * 2 * 128 * APAD * 2;  // 73728 B
    cudaFuncSetAttribute(gemm_1t, cudaFuncAttributeMaxDynamicSharedMemorySize, smemB);

    // 0) convert to fp16
    cvt_h_kernel<<<((size_t)L * DM / 4 + 255) / 256, 256>>>(u, uh, (size_t)L * DM / 4);
    cvt_h_kernel<<<((size_t)DPROJ * DM / 4 + 255) / 256, 256>>>(in_proj_w, wi, (size_t)DPROJ * DM / 4);
    cvt_h_kernel<<<((size_t)DM * DIN / 4 + 255) / 256, 256>>>(out_proj_w, wo, (size_t)DM * DIN / 4);

    // 1) in_proj (fp16 1-term, KC=64)
    gemm_1t<<<dim3((DPROJ + 127) / 128, L / 128), 256, smemB>>>(uh, wi, zx, DPROJ, DM);
    // 2) conv + silu
    conv_kernel<<<((size_t)L * (CONVD / 4) + 255) / 256, 256>>>(conv_w, conv_b);
    // 3) dt softplus
    dt_kernel<<<(2 * L * NH + 255) / 256, 256>>>(dt_bias);
    // 4) B/C prep
    prep_bc_kernel<<<(2 * L * NST + 255) / 256, 256>>>();
    // 5) per-chunk cumsum of A*dt
    acs_kernel<<<dim3(NC, 2), 32>>>(A_log);
    // 6) G = C B^T per (dir,chunk)
    sgemm64_nt<<<dim3(2, 2, 2 * NC), 256>>>(Cm, Bm, G);
    // 7) Y_diag + chunk states (fused single slab loop)
    ydiag_states_kernel<<<2 * NC * NH, 256>>>();
    // 8) inter-chunk recurrence
    recur_kernel<<<512, 256>>>();
    // 9) Y_off + x*D
    yoff_kernel<<<2 * NC * NH, 256>>>(Dv);
    // 10) fd
    fcD_kernel<<<L / 32, 256>>>(fc_D_w, Dv);
    // 11) shift/merge/gate/RMSNorm
    combine_kernel<<<L, 256>>>(norm_w);
    // 12) out_proj (fp16 1-term, KC=64)
    gemm_1t<<<dim3(DM / 128, L / 128), 256, smemB>>>(ynh, wo, out, DM, DIN);
}